// round 11
// baseline (speedup 1.0000x reference)
#include <cuda_runtime.h>
#include <cuda_bf16.h>
#include <math.h>
#include <stdint.h>

#define D 1024
#define TB 4096
#define BATCH 16
typedef unsigned long long ull;

// ---------- scratch: plane-row format, row i = [re(Kc) | im(Kc)] ----------
__device__ __align__(16) float g_Ask[D * 2 * D];
__device__ __align__(16) float g_pA [D * 2 * D];
__device__ __align__(16) float g_pB [D * 2 * D];
__device__ __align__(16) float g_a0 [D * 2 * D];
__device__ __align__(16) float g_a1 [D * 2 * D];
__device__ __align__(16) float g_UV0[D * 2 * D];
__device__ __align__(16) float g_UV1[D * 2 * D];
__device__ __align__(16) float g_Mpl[D * 2 * D];
__device__ __align__(16) float g_X  [D * 2 * D];
__device__ __align__(16) float g_Us [D * 2 * D];
__device__ __align__(16) float g_Usi[D * 2 * D];
__device__ __align__(16) float g_Md [D * 2 * D];
__device__ __align__(16) float g_Mf [D * 2 * D];
__device__ __align__(16) float g_W  [D * 4 * D];
__device__ __align__(16) float g_HX [TB * 4 * D];  // 4096 x 4096
__device__ __align__(16) float g_Cre[TB * D];
__device__ __align__(16) float g_Cim[TB * D];

__device__ float2 g_s[D];
__device__ float2 g_sinv[D];
__device__ float2 g_opd[D];
__device__ float2 g_opf[D];
__device__ float  g_xm  [BATCH * 2 * D];
__device__ float  g_fre [BATCH * D];
__device__ float  g_fim [BATCH * D];
__device__ float  g_proj[BATCH * 2 * D];
__device__ float2 g_Sv  [BATCH * D];
__device__ float2 g_t   [BATCH * D];

__device__ __forceinline__ float2 cmulf(float2 a, float2 b) {
    return make_float2(fmaf(a.x, b.x, -a.y * b.y), fmaf(a.x, b.y, a.y * b.x));
}

__device__ __forceinline__ uint32_t smem_u32(const void* p) {
    uint32_t a;
    asm("{ .reg .u64 t; cvta.to.shared.u64 t, %1; cvt.u32.u64 %0, t; }" : "=r"(a) : "l"(p));
    return a;
}

// split 2 floats into packed bf16x2 hi & lo
__device__ __forceinline__ void bsplit(float a, float b, uint32_t& h, uint32_t& l) {
    __nv_bfloat16 ha = __float2bfloat16_rn(a), hb = __float2bfloat16_rn(b);
    __nv_bfloat16 la = __float2bfloat16_rn(a - __bfloat162float(ha));
    __nv_bfloat16 lb = __float2bfloat16_rn(b - __bfloat162float(hb));
    __nv_bfloat162 H(ha, hb), L(la, lb);
    h = reinterpret_cast<uint32_t&>(H);
    l = reinterpret_cast<uint32_t&>(L);
}

// 8 floats (scaled) -> hi uint4 + lo uint4 (8 bf16 each)
__device__ __forceinline__ void cvt8(float4 u, float4 v, float s, uint4& H, uint4& L) {
    uint32_t h0, h1, h2, h3, l0, l1, l2, l3;
    bsplit(u.x * s, u.y * s, h0, l0);
    bsplit(u.z * s, u.w * s, h1, l1);
    bsplit(v.x * s, v.y * s, h2, l2);
    bsplit(v.z * s, v.w * s, h3, l3);
    H = make_uint4(h0, h1, h2, h3);
    L = make_uint4(l0, l1, l2, l3);
}

__device__ __forceinline__ void ldm_x4(uint32_t* r, uint32_t addr) {
    asm volatile("ldmatrix.sync.aligned.m8n8.x4.shared.b16 {%0,%1,%2,%3}, [%4];"
                 : "=r"(r[0]), "=r"(r[1]), "=r"(r[2]), "=r"(r[3]) : "r"(addr));
}
__device__ __forceinline__ void ldm_x2(uint32_t* r, uint32_t addr) {
    asm volatile("ldmatrix.sync.aligned.m8n8.x2.shared.b16 {%0,%1}, [%2];"
                 : "=r"(r[0]), "=r"(r[1]) : "r"(addr));
}
__device__ __forceinline__ void mma16816(float* d, const uint32_t* a, const uint32_t* b) {
    asm volatile(
        "mma.sync.aligned.m16n8k16.row.col.f32.bf16.bf16.f32 "
        "{%0,%1,%2,%3}, {%4,%5,%6,%7}, {%8,%9}, {%0,%1,%2,%3};"
        : "+f"(d[0]), "+f"(d[1]), "+f"(d[2]), "+f"(d[3])
        : "r"(a[0]), "r"(a[1]), "r"(a[2]), "r"(a[3]), "r"(b[0]), "r"(b[1]));
}

// swizzled smem offset: tile row-major, 64B/row (32 bf16), 16B chunks XOR-swizzled
__device__ __forceinline__ uint32_t swz(int row, int chunk) {
    return (uint32_t)(row * 64 + ((chunk ^ ((row >> 1) & 3)) << 4));
}

// ---------- HMMA GEMM (512 threads, 16 warps of 32x32) ----------
// C[m,n'] = sum over K2=2Kc of Arow[m,q] * Bop[n',q]; complex embedded,
// 3-term bf16 split (AhBh + AlBh + AhBl). Block 128x128, 16 warps 32x32.
struct GP {
    const float* A;   // Mrows x 2Kc fp32
    const float* B;   // Nc(=D) x 2Kc fp32
    float* Cre; float* Cim; int ldc;
    const float* Ere; const float* Eim; int lde;
    float sgnr, sgni;
};

#define A_HI 0
#define A_LO 8192
#define B_HI 16384
#define B_LO 24576
#define STG 32768
#define SMEM_TOT (2 * STG)
#define NTHREADS 512

__global__ void __launch_bounds__(NTHREADS, 1) hmma_gemm(GP p, int Kc) {
    extern __shared__ __align__(128) uint8_t sm[];
    const uint32_t sb = smem_u32(sm);
    const int tid = threadIdx.x;
    const int lane = tid & 31;
    const int wid = tid >> 5;
    const int wm = (wid & 3) * 32;
    const int wn = (wid >> 2) * 32;
    const int K2 = 2 * Kc;
    const int Nc = D;
    const int m0 = blockIdx.x * 128;
    const int n0 = blockIdx.y * 128;
    const int isim_n = (n0 >= Nc);
    const int nsrc0 = n0 - (isim_n ? Nc : 0);
    const int T = K2 >> 5;

    float acc[2][4][4];
#pragma unroll
    for (int i = 0; i < 2; ++i)
#pragma unroll
        for (int j = 0; j < 4; ++j)
#pragma unroll
            for (int k = 0; k < 4; ++k) acc[i][j][k] = 0.f;

    float4 sa[2], sbv[2];  // one 8-float chunk of A and of B per thread

    auto stage = [&](int t) {
        const int kb = t << 5;
        const int isim_k = (kb >= Kc);
        const int qoff = kb - (isim_k ? Kc : 0);
        const int pl = isim_n ? (1 - isim_k) : isim_k;
        const int bcol = pl * Kc + qoff;
        int row = tid >> 2, c = tid & 3;  // 128 rows x 4 chunks of 8 floats
        const float* ap = p.A + (size_t)(m0 + row) * K2 + kb + c * 8;
        sa[0] = *reinterpret_cast<const float4*>(ap);
        sa[1] = *reinterpret_cast<const float4*>(ap + 4);
        const float* bp = p.B + (size_t)(nsrc0 + row) * K2 + bcol + c * 8;
        sbv[0] = *reinterpret_cast<const float4*>(bp);
        sbv[1] = *reinterpret_cast<const float4*>(bp + 4);
    };
    auto sts = [&](int t) {
        const int kb = t << 5;
        const int isim_k = (kb >= Kc);
        const int pl = isim_n ? (1 - isim_k) : isim_k;
        const float sg = ((!isim_n && isim_k) ? -1.f : 1.f) * (pl ? p.sgni : p.sgnr);
        uint8_t* sbuf = sm + (size_t)(t & 1) * STG;
        int row = tid >> 2, c = tid & 3;
        uint32_t off = swz(row, c);
        uint4 H, L;
        cvt8(sa[0], sa[1], 1.f, H, L);
        *reinterpret_cast<uint4*>(sbuf + A_HI + off) = H;
        *reinterpret_cast<uint4*>(sbuf + A_LO + off) = L;
        cvt8(sbv[0], sbv[1], sg, H, L);
        *reinterpret_cast<uint4*>(sbuf + B_HI + off) = H;
        *reinterpret_cast<uint4*>(sbuf + B_LO + off) = L;
    };

    stage(0);
    sts(0);
    __syncthreads();

    for (int t = 0; t < T; ++t) {
        if (t + 1 < T) stage(t + 1);
        const uint32_t sbb = sb + (uint32_t)(t & 1) * STG;
#pragma unroll
        for (int k16 = 0; k16 < 2; ++k16) {
            uint32_t ah[2][4], al[2][4], bh[4][2], bl[4][2];
            int amat = lane >> 3;
            int arow_off = (lane & 7) + ((amat & 1) << 3);
            int achk = 2 * k16 + (amat >> 1);
#pragma unroll
            for (int mf = 0; mf < 2; ++mf) {
                int r = wm + mf * 16 + arow_off;
                uint32_t off = swz(r, achk);
                ldm_x4(ah[mf], sbb + A_HI + off);
                ldm_x4(al[mf], sbb + A_LO + off);
            }
            // B: smem holds Bop[n][k] (N x K row-major) == col-major B -> NON-trans ldmatrix
            int bmat = (lane & 15) >> 3;
            int brow_off = lane & 7;
            int bchk = 2 * k16 + bmat;
#pragma unroll
            for (int nf = 0; nf < 4; ++nf) {
                int r = wn + nf * 8 + brow_off;
                uint32_t off = swz(r, bchk);
                ldm_x2(bh[nf], sbb + B_HI + off);
                ldm_x2(bl[nf], sbb + B_LO + off);
            }
#pragma unroll
            for (int mf = 0; mf < 2; ++mf)
#pragma unroll
                for (int nf = 0; nf < 4; ++nf) {
                    mma16816(acc[mf][nf], ah[mf], bh[nf]);
                    mma16816(acc[mf][nf], al[mf], bh[nf]);
                    mma16816(acc[mf][nf], ah[mf], bl[nf]);
                }
        }
        if (t + 1 < T) sts(t + 1);
        __syncthreads();
    }

    float* op = isim_n ? p.Cim : p.Cre;
    const float* ep = isim_n ? p.Eim : p.Ere;
#pragma unroll
    for (int mf = 0; mf < 2; ++mf) {
        int r0 = m0 + wm + mf * 16 + (lane >> 2);
#pragma unroll
        for (int nf = 0; nf < 4; ++nf) {
            int col = nsrc0 + wn + nf * 8 + (lane & 3) * 2;
            float2 v0 = make_float2(acc[mf][nf][0], acc[mf][nf][1]);
            float2 v1 = make_float2(acc[mf][nf][2], acc[mf][nf][3]);
            if (p.Ere) {
                v0.x += ep[(size_t)r0 * p.lde + col];
                v0.y += ep[(size_t)r0 * p.lde + col + 1];
                v1.x += ep[(size_t)(r0 + 8) * p.lde + col];
                v1.y += ep[(size_t)(r0 + 8) * p.lde + col + 1];
            }
            *reinterpret_cast<float2*>(&op[(size_t)r0 * p.ldc + col]) = v0;
            *reinterpret_cast<float2*>(&op[(size_t)(r0 + 8) * p.ldc + col]) = v1;
        }
    }
}

// ---------- small kernels ----------
__global__ void k_buildA(float* __restrict__ A, const float* __restrict__ re,
                         const float* __restrict__ im) {
    int idx = blockIdx.x * 256 + threadIdx.x;
    int i = idx >> 10, j = idx & (D - 1);
    A[(size_t)i * 2048 + j] = 0.5f * (re[i * D + j] - re[j * D + i]);
    A[(size_t)i * 2048 + D + j] = 0.5f * (im[i * D + j] + im[j * D + i]);
}

__global__ void k_g0(float* __restrict__ ACC, const float* __restrict__ A,
                     const float* __restrict__ P) {
    int idx = blockIdx.x * 256 + threadIdx.x;
    int i = idx >> 10, j = idx & (D - 1);
    size_t rr = (size_t)i * 2048 + j, ri = rr + D;
    float dgl = (i == j) ? 1.f : 0.f;
    ACC[rr] = dgl + 2.f * A[rr] + P[rr];
    ACC[ri] = 2.f * A[ri] + P[ri];
}

__global__ void k_colscale(float* __restrict__ dst, const float* __restrict__ src,
                           const float2* __restrict__ c) {
    int idx = blockIdx.x * 256 + threadIdx.x;
    int i = idx >> 10, j = idx & (D - 1);
    size_t rr = (size_t)i * 2048 + j, ri = rr + D;
    float sr = src[rr], si = src[ri];
    float2 cc = c[j];
    dst[rr] = sr * cc.x - si * cc.y;
    dst[ri] = sr * cc.y + si * cc.x;
}

__global__ void k_scales(const float* __restrict__ ls) {
    int d = blockIdx.x * 256 + threadIdx.x;
    if (d >= D) return;
    g_s[d] = make_float2(expf(ls[d]), 0.f);
    g_sinv[d] = make_float2(expf(-ls[d]), 0.f);
}

__global__ void k_ops(const float* __restrict__ ld_, const float* __restrict__ lf_,
                      const float* __restrict__ lawre, const float* __restrict__ lawim,
                      const float* __restrict__ dtp) {
    int d = blockIdx.x * 256 + threadIdx.x;
    if (d >= D) return;
    float dtv = dtp[0];
    float lre = -expf(ld_[d]) + lawre[d];
    float lim = lf_[d] + lawim[d];
    float z = -lre;
    float sp = (z > 0.f) ? (z + log1pf(expf(-z))) : log1pf(expf(z));
    float2 Z = make_float2(-sp * dtv, lim * dtv);
    float ex = expf(Z.x);
    float sy, cy;
    sincosf(Z.y, &sy, &cy);
    float2 ez = make_float2(ex * cy, ex * sy);
    g_opd[d] = ez;
    float az2 = Z.x * Z.x + Z.y * Z.y;
    float2 phi;
    if (sqrtf(az2) < 1e-4f) {
        float2 z2 = cmulf(Z, Z);
        phi = make_float2(1.f + 0.5f * Z.x + z2.x * (1.f / 6.f), 0.5f * Z.y + z2.y * (1.f / 6.f));
    } else {
        float2 num = make_float2(ez.x - 1.f, ez.y);
        float inv = 1.f / az2;
        phi = make_float2((num.x * Z.x + num.y * Z.y) * inv, (num.y * Z.x - num.x * Z.y) * inv);
    }
    g_opf[d] = make_float2(phi.x * dtv, phi.y * dtv);
}

__global__ void k_smallgemm(const float* __restrict__ lo, const float* __restrict__ hi,
                            const float* __restrict__ w, const float* __restrict__ bias,
                            float* __restrict__ outp) {
    int o = blockIdx.x;
    int tid = threadIdx.x;
    float part[BATCH];
#pragma unroll
    for (int b = 0; b < BATCH; ++b) part[b] = 0.f;
    const float* wr = w + (size_t)o * (2 * D);
    for (int k = tid; k < 2 * D; k += 128) {
        float wv = wr[k];
        const float* src = (k < D) ? (lo + k) : (hi + (k - D));
#pragma unroll
        for (int b = 0; b < BATCH; ++b) part[b] = fmaf(src[b * D], wv, part[b]);
    }
    __shared__ float red[BATCH][128];
#pragma unroll
    for (int b = 0; b < BATCH; ++b) red[b][tid] = part[b];
    __syncthreads();
    if (tid < BATCH) {
        float sv = bias[o];
#pragma unroll 8
        for (int j = 0; j < 128; ++j) sv += red[tid][j];
        outp[tid * 2 * D + o] = sv;
    }
}

__global__ void k_flux(const float* __restrict__ fre, const float* __restrict__ fim,
                       const float* __restrict__ dre, const float* __restrict__ dim_,
                       const float* __restrict__ xm, float* __restrict__ out) {
    int idx = blockIdx.x * 256 + threadIdx.x;
    int b = idx >> 10, d = idx & (D - 1);
    float2 dec = make_float2(1.f / (1.f + expf(-dre[d])), dim_[d]);
    float2 f = make_float2(fre[idx], fim[idx]);
    float2 fn = cmulf(f, dec);
    fn.x += xm[b * 2 * D + d];
    fn.y += xm[b * 2 * D + D + d];
    g_fre[idx] = fn.x;
    g_fim[idx] = fn.y;
    out[2 * TB * D + idx] = fn.x;
    out[2 * TB * D + BATCH * D + idx] = fn.y;
}

__global__ void k_source(const float* __restrict__ proj) {
    int idx = blockIdx.x * 256 + threadIdx.x;
    int b = idx >> 10, d = idx & (D - 1);
    float2 src = make_float2(proj[b * 2 * D + d], proj[b * 2 * D + D + d]);
    g_Sv[idx] = cmulf(g_opf[d], src);
}

__global__ void k_tsmall() {
    int i = blockIdx.x;
    int tid = threadIdx.x;
    float2 part[BATCH];
#pragma unroll
    for (int b = 0; b < BATCH; ++b) part[b] = make_float2(0.f, 0.f);
    for (int j = tid; j < D; j += 128) {
        float2 m = make_float2(g_Mpl[(size_t)i * 2048 + j], g_Mpl[(size_t)i * 2048 + D + j]);
#pragma unroll
        for (int b = 0; b < BATCH; ++b) {
            float2 sv = g_Sv[b * D + j];
            part[b].x = fmaf(m.x, sv.x, fmaf(-m.y, sv.y, part[b].x));
            part[b].y = fmaf(m.x, sv.y, fmaf(m.y, sv.x, part[b].y));
        }
    }
    __shared__ float2 red[BATCH][128];
#pragma unroll
    for (int b = 0; b < BATCH; ++b) red[b][tid] = part[b];
    __syncthreads();
    if (tid < BATCH) {
        float2 sv = make_float2(0.f, 0.f);
#pragma unroll 8
        for (int j = 0; j < 128; ++j) { sv.x += red[tid][j].x; sv.y += red[tid][j].y; }
        g_t[tid * D + i] = sv;
    }
}

// HX row n = [hre | xre | him | xim]
__global__ void k_pack(const float* __restrict__ hre, const float* __restrict__ him,
                       const float* __restrict__ xre, const float* __restrict__ xim) {
    int idx = blockIdx.x * 256 + threadIdx.x;  // TB*D
    int n = idx >> 10, k = idx & (D - 1);
    size_t rb = (size_t)n * 4096;
    g_HX[rb + k] = hre[idx];
    g_HX[rb + D + k] = xre[idx];
    g_HX[rb + 2 * D + k] = him[idx];
    g_HX[rb + 3 * D + k] = xim[idx];
}

__global__ void k_epi(float* __restrict__ out) {
    int idx = blockIdx.x * 256 + threadIdx.x;  // TB*D
    int n = idx >> 10, i = idx & (D - 1);
    int b = n >> 8;
    float2 tv = g_t[b * D + i];
    out[idx] = g_Cre[idx] + tv.x;
    out[TB * D + idx] = g_Cim[idx] + tv.y;
}

// ---------- host ----------
static float* symf(const void* s) {
    void* p = nullptr;
    cudaGetSymbolAddress(&p, s);
    return (float*)p;
}
static float2* symf2(const void* s) {
    void* p = nullptr;
    cudaGetSymbolAddress(&p, s);
    return (float2*)p;
}

static void gemm(const float* A, const float* B, float sr, float si, float* Cre, float* Cim,
                 int ldc, const float* Ere, const float* Eim, int lde, int Kc, int Mrows) {
    GP p;
    p.A = A; p.B = B; p.Cre = Cre; p.Cim = Cim; p.ldc = ldc;
    p.Ere = Ere; p.Eim = Eim; p.lde = lde; p.sgnr = sr; p.sgni = si;
    dim3 g(Mrows / 128, 16, 1);
    hmma_gemm<<<g, NTHREADS, SMEM_TOT>>>(p, Kc);
}

static void chain(const float* re, const float* im, float* UV) {
    float* As = symf(g_Ask);
    float* pA = symf(g_pA);
    float* pB = symf(g_pB);
    float* a0 = symf(g_a0);
    float* a1 = symf(g_a1);
    k_buildA<<<4096, 256>>>(As, re, im);
    gemm(As, As, -1.f, 1.f, pA, pA + D, 2048, 0, 0, 0, D, D);          // P2 = A*A
    k_g0<<<4096, 256>>>(a0, As, pA);                                    // ACC0 = (I+A)^2
    gemm(a0, pA, 1.f, -1.f, a1, a1 + D, 2048, a0, a0 + D, 2048, D, D);  // ACC1
    gemm(pA, pA, 1.f, -1.f, pB, pB + D, 2048, 0, 0, 0, D, D);           // P4
    gemm(a1, pB, 1.f, -1.f, a0, a0 + D, 2048, a1, a1 + D, 2048, D, D);  // ACC2
    gemm(pB, pB, 1.f, -1.f, pA, pA + D, 2048, 0, 0, 0, D, D);           // P8
    gemm(a0, pA, 1.f, -1.f, a1, a1 + D, 2048, a0, a0 + D, 2048, D, D);  // ACC3
    gemm(pA, pA, 1.f, -1.f, pB, pB + D, 2048, 0, 0, 0, D, D);           // P16
    gemm(a1, pB, 1.f, -1.f, UV, UV + D, 2048, a1, a1 + D, 2048, D, D);  // UV
}

extern "C" void kernel_launch(void* const* d_in, const int* in_sizes, int n_in,
                              void* d_out, int out_size) {
    const float* h_re = (const float*)d_in[0];
    const float* h_im = (const float*)d_in[1];
    const float* x_re = (const float*)d_in[2];
    const float* x_im = (const float*)d_in[3];
    const float* xg_re = (const float*)d_in[4];
    const float* xg_im = (const float*)d_in[5];
    const float* fl_re = (const float*)d_in[6];
    const float* fl_im = (const float*)d_in[7];
    const float* dt = (const float*)d_in[8];
    const float* u_re = (const float*)d_in[9];
    const float* u_im = (const float*)d_in[10];
    const float* v_re = (const float*)d_in[11];
    const float* v_im = (const float*)d_in[12];
    const float* lsig = (const float*)d_in[13];
    const float* dec_re = (const float*)d_in[14];
    const float* dec_im = (const float*)d_in[15];
    const float* mix_w = (const float*)d_in[16];
    const float* mix_b = (const float*)d_in[17];
    const float* proj_w = (const float*)d_in[18];
    const float* proj_b = (const float*)d_in[19];
    const float* ld_ = (const float*)d_in[20];
    const float* lf_ = (const float*)d_in[21];
    const float* law_re = (const float*)d_in[22];
    const float* law_im = (const float*)d_in[23];
    float* out = (float*)d_out;

    cudaFuncSetAttribute(hmma_gemm, cudaFuncAttributeMaxDynamicSharedMemorySize, SMEM_TOT);

    float* UV0 = symf(g_UV0);
    float* UV1 = symf(g_UV1);
    float* Mpl = symf(g_Mpl);
    float* X = symf(g_X);
    float* Us = symf(g_Us);
    float* Usi = symf(g_Usi);
    float* Md = symf(g_Md);
    float* Mf = symf(g_Mf);
    float* W = symf(g_W);
    float* HX = symf(g_HX);
    float* Cre = symf(g_Cre);
    float* Cim = symf(g_Cim);
    float2* sd = symf2(g_s);
    float2* sinv = symf2(g_sinv);
    float2* opd = symf2(g_opd);
    float2* opf = symf2(g_opf);
    float* xm = symf(g_xm);
    float* fre = symf(g_fre);
    float* fim = symf(g_fim);
    float* proj = symf(g_proj);

    chain(u_re, u_im, UV0);  // U
    chain(v_re, v_im, UV1);  // V

    k_scales<<<4, 256>>>(lsig);
    k_ops<<<4, 256>>>(ld_, lf_, law_re, law_im, dt);

    k_colscale<<<4096, 256>>>(Us, UV0, sd);
    k_colscale<<<4096, 256>>>(Usi, UV0, sinv);
    gemm(Us, UV1, 1.f, -1.f, Mpl, Mpl + D, 2048, 0, 0, 0, D, D);   // M = (U s) V^H
    gemm(Usi, UV1, 1.f, -1.f, X, X + D, 2048, 0, 0, 0, D, D);      // X = (U s^-1) V^H
    k_colscale<<<4096, 256>>>(Md, Mpl, opd);
    k_colscale<<<4096, 256>>>(Mf, Mpl, opf);
    // W1 = Md @ Minv (Minv row-read = conj rows of X) ; W row = [W1r|W2r|W1i|W2i]
    gemm(Md, X, 1.f, -1.f, W, W + 2 * D, 4096, 0, 0, 0, D, D);       // W1
    gemm(Mf, X, 1.f, -1.f, W + D, W + 3 * D, 4096, 0, 0, 0, D, D);   // W2

    k_smallgemm<<<2 * D, 128>>>(xg_re, xg_im, mix_w, mix_b, xm);
    k_flux<<<BATCH * D / 256, 256>>>(fl_re, fl_im, dec_re, dec_im, xm, out);
    k_smallgemm<<<2 * D, 128>>>(fre, fim, proj_w, proj_b, proj);
    k_source<<<BATCH * D / 256, 256>>>(proj);
    k_tsmall<<<D, 128>>>();

    k_pack<<<TB * D / 256, 256>>>(h_re, h_im, x_re, x_im);
    gemm(HX, W, 1.f, 1.f, Cre, Cim, D, 0, 0, 0, 2 * D, TB);  // main
    k_epi<<<TB * D / 256, 256>>>(out);

    (void)in_sizes; (void)n_in; (void)out_size;
}

// round 12
// speedup vs baseline: 1.1487x; 1.1487x over previous
#include <cuda_runtime.h>
#include <cuda_bf16.h>
#include <math.h>
#include <stdint.h>

#define D 1024
#define TB 4096
#define BATCH 16
typedef unsigned long long ull;

// ---------- scratch: plane-row format, row i = [re(Kc) | im(Kc)], ld 2048 ----------
__device__ __align__(16) float g_AsU[D * 2 * D];
__device__ __align__(16) float g_AsV[D * 2 * D];
__device__ __align__(16) float g_pAU[D * 2 * D];
__device__ __align__(16) float g_pAV[D * 2 * D];
__device__ __align__(16) float g_pBU[D * 2 * D];
__device__ __align__(16) float g_pBV[D * 2 * D];
__device__ __align__(16) float g_a0U[D * 2 * D];
__device__ __align__(16) float g_a0V[D * 2 * D];
__device__ __align__(16) float g_a1U[D * 2 * D];
__device__ __align__(16) float g_a1V[D * 2 * D];
__device__ __align__(16) float g_UV0[D * 2 * D];
__device__ __align__(16) float g_UV1[D * 2 * D];
__device__ __align__(16) float g_Mpl[D * 2 * D];
__device__ __align__(16) float g_X  [D * 2 * D];
__device__ __align__(16) float g_Us [D * 2 * D];
__device__ __align__(16) float g_Usi[D * 2 * D];
__device__ __align__(16) float g_Md [D * 2 * D];
__device__ __align__(16) float g_Mf [D * 2 * D];
__device__ __align__(16) float g_W  [D * 4 * D];
__device__ __align__(16) float g_HX [TB * 4 * D];
__device__ __align__(16) float g_Cre[TB * D];
__device__ __align__(16) float g_Cim[TB * D];

__device__ float2 g_s[D];
__device__ float2 g_sinv[D];
__device__ float2 g_opd[D];
__device__ float2 g_opf[D];
__device__ float  g_xm  [BATCH * 2 * D];
__device__ float  g_fre [BATCH * D];
__device__ float  g_fim [BATCH * D];
__device__ float  g_proj[BATCH * 2 * D];
__device__ float2 g_Sv  [BATCH * D];
__device__ float2 g_t   [BATCH * D];

__device__ __forceinline__ float2 cmulf(float2 a, float2 b) {
    return make_float2(fmaf(a.x, b.x, -a.y * b.y), fmaf(a.x, b.y, a.y * b.x));
}

__device__ __forceinline__ uint32_t smem_u32(const void* p) {
    uint32_t a;
    asm("{ .reg .u64 t; cvta.to.shared.u64 t, %1; cvt.u32.u64 %0, t; }" : "=r"(a) : "l"(p));
    return a;
}

__device__ __forceinline__ void bsplit(float a, float b, uint32_t& h, uint32_t& l) {
    __nv_bfloat16 ha = __float2bfloat16_rn(a), hb = __float2bfloat16_rn(b);
    __nv_bfloat16 la = __float2bfloat16_rn(a - __bfloat162float(ha));
    __nv_bfloat16 lb = __float2bfloat16_rn(b - __bfloat162float(hb));
    __nv_bfloat162 H(ha, hb), L(la, lb);
    h = reinterpret_cast<uint32_t&>(H);
    l = reinterpret_cast<uint32_t&>(L);
}

__device__ __forceinline__ void cvt8(float4 u, float4 v, float s, uint4& H, uint4& L) {
    uint32_t h0, h1, h2, h3, l0, l1, l2, l3;
    bsplit(u.x * s, u.y * s, h0, l0);
    bsplit(u.z * s, u.w * s, h1, l1);
    bsplit(v.x * s, v.y * s, h2, l2);
    bsplit(v.z * s, v.w * s, h3, l3);
    H = make_uint4(h0, h1, h2, h3);
    L = make_uint4(l0, l1, l2, l3);
}

__device__ __forceinline__ void ldm_x4(uint32_t* r, uint32_t addr) {
    asm volatile("ldmatrix.sync.aligned.m8n8.x4.shared.b16 {%0,%1,%2,%3}, [%4];"
                 : "=r"(r[0]), "=r"(r[1]), "=r"(r[2]), "=r"(r[3]) : "r"(addr));
}
__device__ __forceinline__ void ldm_x2(uint32_t* r, uint32_t addr) {
    asm volatile("ldmatrix.sync.aligned.m8n8.x2.shared.b16 {%0,%1}, [%2];"
                 : "=r"(r[0]), "=r"(r[1]) : "r"(addr));
}
__device__ __forceinline__ void mma16816(float* d, const uint32_t* a, const uint32_t* b) {
    asm volatile(
        "mma.sync.aligned.m16n8k16.row.col.f32.bf16.bf16.f32 "
        "{%0,%1,%2,%3}, {%4,%5,%6,%7}, {%8,%9}, {%0,%1,%2,%3};"
        : "+f"(d[0]), "+f"(d[1]), "+f"(d[2]), "+f"(d[3])
        : "r"(a[0]), "r"(a[1]), "r"(a[2]), "r"(a[3]), "r"(b[0]), "r"(b[1]));
}

__device__ __forceinline__ uint32_t swz(int row, int chunk) {
    return (uint32_t)(row * 64 + ((chunk ^ ((row >> 1) & 3)) << 4));
}

// ---------- HMMA GEMM (round-9 engine + z-fusion + upper-tri mode) ----------
struct GP {
    const float* A;
    const float* B;
    float* Cre; float* Cim; int ldc;
    const float* Ere; const float* Eim; int lde;
    float sgnr, sgni;
};

#define A_HI 0
#define A_LO 8192
#define B_HI 16384
#define B_LO 24576

__global__ void __launch_bounds__(256, 1) hmma_gemm(GP p0, GP p1, int Kc, int tri) {
    __shared__ __align__(128) uint8_t sm[32768];
    const GP p = blockIdx.z ? p1 : p0;
    const uint32_t sb = smem_u32(sm);
    const int tid = threadIdx.x;
    const int lane = tid & 31;
    const int wid = tid >> 5;
    const int wm = (wid & 1) * 64;
    const int wn = (wid >> 1) * 32;
    const int K2 = 2 * Kc;
    const int Nc = D;

    int m0, n0;
    if (tri) {
        int k = blockIdx.x;
        int plane = 0;
        if (k >= 36) { plane = 1; k -= 36; }
        int mi = 0;
        while (k >= 8 - mi) { k -= 8 - mi; ++mi; }
        m0 = mi * 128;
        n0 = plane * D + (mi + k) * 128;
    } else {
        m0 = blockIdx.x * 128;
        n0 = blockIdx.y * 128;
    }
    const int isim_n = (n0 >= Nc);
    const int nsrc0 = n0 - (isim_n ? Nc : 0);
    const int T = K2 >> 5;

    float acc[4][4][4];
#pragma unroll
    for (int i = 0; i < 4; ++i)
#pragma unroll
        for (int j = 0; j < 4; ++j)
#pragma unroll
            for (int k = 0; k < 4; ++k) acc[i][j][k] = 0.f;

    float4 sa[2][2], sbv[2][2];

    auto stage = [&](int t) {
        const int kb = t << 5;
        const int isim_k = (kb >= Kc);
        const int qoff = kb - (isim_k ? Kc : 0);
        const int pl = isim_n ? (1 - isim_k) : isim_k;
        const int bcol = pl * Kc + qoff;
#pragma unroll
        for (int i = 0; i < 2; ++i) {
            int task = tid + (i << 8);
            int row = task >> 2, c = task & 3;
            const float* ap = p.A + (size_t)(m0 + row) * K2 + kb + c * 8;
            sa[i][0] = *reinterpret_cast<const float4*>(ap);
            sa[i][1] = *reinterpret_cast<const float4*>(ap + 4);
            const float* bp = p.B + (size_t)(nsrc0 + row) * K2 + bcol + c * 8;
            sbv[i][0] = *reinterpret_cast<const float4*>(bp);
            sbv[i][1] = *reinterpret_cast<const float4*>(bp + 4);
        }
    };
    auto sts = [&](int t) {
        const int kb = t << 5;
        const int isim_k = (kb >= Kc);
        const int pl = isim_n ? (1 - isim_k) : isim_k;
        const float sg = ((!isim_n && isim_k) ? -1.f : 1.f) * (pl ? p.sgni : p.sgnr);
#pragma unroll
        for (int i = 0; i < 2; ++i) {
            int task = tid + (i << 8);
            int row = task >> 2, c = task & 3;
            uint32_t off = swz(row, c);
            uint4 H, L;
            cvt8(sa[i][0], sa[i][1], 1.f, H, L);
            *reinterpret_cast<uint4*>(sm + A_HI + off) = H;
            *reinterpret_cast<uint4*>(sm + A_LO + off) = L;
            cvt8(sbv[i][0], sbv[i][1], sg, H, L);
            *reinterpret_cast<uint4*>(sm + B_HI + off) = H;
            *reinterpret_cast<uint4*>(sm + B_LO + off) = L;
        }
    };

    stage(0);
    for (int t = 0; t < T; ++t) {
        sts(t);
        __syncthreads();
        if (t + 1 < T) stage(t + 1);
#pragma unroll
        for (int k16 = 0; k16 < 2; ++k16) {
            uint32_t ah[4][4], al[4][4], bh[4][2], bl[4][2];
            int amat = lane >> 3;
            int arow_off = (lane & 7) + ((amat & 1) << 3);
            int achk = 2 * k16 + (amat >> 1);
#pragma unroll
            for (int mf = 0; mf < 4; ++mf) {
                int r = wm + mf * 16 + arow_off;
                uint32_t off = swz(r, achk);
                ldm_x4(ah[mf], sb + A_HI + off);
                ldm_x4(al[mf], sb + A_LO + off);
            }
            int bmat = (lane & 15) >> 3;
            int brow_off = lane & 7;
            int bchk = 2 * k16 + bmat;
#pragma unroll
            for (int nf = 0; nf < 4; ++nf) {
                int r = wn + nf * 8 + brow_off;
                uint32_t off = swz(r, bchk);
                ldm_x2(bh[nf], sb + B_HI + off);
                ldm_x2(bl[nf], sb + B_LO + off);
            }
#pragma unroll
            for (int mf = 0; mf < 4; ++mf)
#pragma unroll
                for (int nf = 0; nf < 4; ++nf) {
                    mma16816(acc[mf][nf], ah[mf], bh[nf]);
                    mma16816(acc[mf][nf], al[mf], bh[nf]);
                    mma16816(acc[mf][nf], ah[mf], bl[nf]);
                }
        }
        __syncthreads();
    }

    float* op = isim_n ? p.Cim : p.Cre;
    const float* ep = isim_n ? p.Eim : p.Ere;
#pragma unroll
    for (int mf = 0; mf < 4; ++mf) {
        int r0 = m0 + wm + mf * 16 + (lane >> 2);
#pragma unroll
        for (int nf = 0; nf < 4; ++nf) {
            int col = nsrc0 + wn + nf * 8 + (lane & 3) * 2;
            float2 v0 = make_float2(acc[mf][nf][0], acc[mf][nf][1]);
            float2 v1 = make_float2(acc[mf][nf][2], acc[mf][nf][3]);
            if (p.Ere) {
                v0.x += ep[(size_t)r0 * p.lde + col];
                v0.y += ep[(size_t)r0 * p.lde + col + 1];
                v1.x += ep[(size_t)(r0 + 8) * p.lde + col];
                v1.y += ep[(size_t)(r0 + 8) * p.lde + col + 1];
            }
            *reinterpret_cast<float2*>(&op[(size_t)r0 * p.ldc + col]) = v0;
            *reinterpret_cast<float2*>(&op[(size_t)(r0 + 8) * p.ldc + col]) = v1;
        }
    }
}

// ---------- small kernels ----------
__global__ void k_buildA2(float* __restrict__ AU, float* __restrict__ AV,
                          const float* __restrict__ reU, const float* __restrict__ imU,
                          const float* __restrict__ reV, const float* __restrict__ imV) {
    int idx = blockIdx.x * 256 + threadIdx.x;
    int i = idx >> 10, j = idx & (D - 1);
    float* A = blockIdx.y ? AV : AU;
    const float* re = blockIdx.y ? reV : reU;
    const float* im = blockIdx.y ? imV : imU;
    A[(size_t)i * 2048 + j] = 0.5f * (re[i * D + j] - re[j * D + i]);
    A[(size_t)i * 2048 + D + j] = 0.5f * (im[i * D + j] + im[j * D + i]);
}

// mirror lower triangle of Hermitian plane matrix from upper
__global__ void k_mirror2(float* __restrict__ P0, float* __restrict__ P1) {
    int idx = blockIdx.x * 256 + threadIdx.x;
    int i = idx >> 10, j = idx & (D - 1);
    if (i <= j) return;
    float* P = blockIdx.y ? P1 : P0;
    P[(size_t)i * 2048 + j] = P[(size_t)j * 2048 + i];
    P[(size_t)i * 2048 + D + j] = -P[(size_t)j * 2048 + D + i];
}

__global__ void k_g02(float* __restrict__ a0U, const float* __restrict__ AU,
                      const float* __restrict__ PU, float* __restrict__ a0V,
                      const float* __restrict__ AV, const float* __restrict__ PV) {
    int idx = blockIdx.x * 256 + threadIdx.x;
    int i = idx >> 10, j = idx & (D - 1);
    float* ACC = blockIdx.y ? a0V : a0U;
    const float* A = blockIdx.y ? AV : AU;
    const float* P = blockIdx.y ? PV : PU;
    size_t rr = (size_t)i * 2048 + j, ri = rr + D;
    float dgl = (i == j) ? 1.f : 0.f;
    ACC[rr] = dgl + 2.f * A[rr] + P[rr];
    ACC[ri] = 2.f * A[ri] + P[ri];
}

__global__ void k_colscale2(float* __restrict__ d0, const float2* __restrict__ c0,
                            float* __restrict__ d1, const float2* __restrict__ c1,
                            const float* __restrict__ src) {
    int idx = blockIdx.x * 256 + threadIdx.x;
    int i = idx >> 10, j = idx & (D - 1);
    float* dst = blockIdx.y ? d1 : d0;
    float2 cc = (blockIdx.y ? c1 : c0)[j];
    size_t rr = (size_t)i * 2048 + j, ri = rr + D;
    float sr = src[rr], si = src[ri];
    dst[rr] = sr * cc.x - si * cc.y;
    dst[ri] = sr * cc.y + si * cc.x;
}

__global__ void k_scales(const float* __restrict__ ls) {
    int d = blockIdx.x * 256 + threadIdx.x;
    if (d >= D) return;
    g_s[d] = make_float2(expf(ls[d]), 0.f);
    g_sinv[d] = make_float2(expf(-ls[d]), 0.f);
}

__global__ void k_ops(const float* __restrict__ ld_, const float* __restrict__ lf_,
                      const float* __restrict__ lawre, const float* __restrict__ lawim,
                      const float* __restrict__ dtp) {
    int d = blockIdx.x * 256 + threadIdx.x;
    if (d >= D) return;
    float dtv = dtp[0];
    float lre = -expf(ld_[d]) + lawre[d];
    float lim = lf_[d] + lawim[d];
    float z = -lre;
    float sp = (z > 0.f) ? (z + log1pf(expf(-z))) : log1pf(expf(z));
    float2 Z = make_float2(-sp * dtv, lim * dtv);
    float ex = expf(Z.x);
    float sy, cy;
    sincosf(Z.y, &sy, &cy);
    float2 ez = make_float2(ex * cy, ex * sy);
    g_opd[d] = ez;
    float az2 = Z.x * Z.x + Z.y * Z.y;
    float2 phi;
    if (sqrtf(az2) < 1e-4f) {
        float2 z2 = cmulf(Z, Z);
        phi = make_float2(1.f + 0.5f * Z.x + z2.x * (1.f / 6.f), 0.5f * Z.y + z2.y * (1.f / 6.f));
    } else {
        float2 num = make_float2(ez.x - 1.f, ez.y);
        float inv = 1.f / az2;
        phi = make_float2((num.x * Z.x + num.y * Z.y) * inv, (num.y * Z.x - num.x * Z.y) * inv);
    }
    g_opf[d] = make_float2(phi.x * dtv, phi.y * dtv);
}

__global__ void k_smallgemm(const float* __restrict__ lo, const float* __restrict__ hi,
                            const float* __restrict__ w, const float* __restrict__ bias,
                            float* __restrict__ outp) {
    int o = blockIdx.x;
    int tid = threadIdx.x;
    float part[BATCH];
#pragma unroll
    for (int b = 0; b < BATCH; ++b) part[b] = 0.f;
    const float* wr = w + (size_t)o * (2 * D);
    for (int k = tid; k < 2 * D; k += 128) {
        float wv = wr[k];
        const float* src = (k < D) ? (lo + k) : (hi + (k - D));
#pragma unroll
        for (int b = 0; b < BATCH; ++b) part[b] = fmaf(src[b * D], wv, part[b]);
    }
    __shared__ float red[BATCH][128];
#pragma unroll
    for (int b = 0; b < BATCH; ++b) red[b][tid] = part[b];
    __syncthreads();
    if (tid < BATCH) {
        float sv = bias[o];
#pragma unroll 8
        for (int j = 0; j < 128; ++j) sv += red[tid][j];
        outp[tid * 2 * D + o] = sv;
    }
}

__global__ void k_flux(const float* __restrict__ fre, const float* __restrict__ fim,
                       const float* __restrict__ dre, const float* __restrict__ dim_,
                       const float* __restrict__ xm, float* __restrict__ out) {
    int idx = blockIdx.x * 256 + threadIdx.x;
    int b = idx >> 10, d = idx & (D - 1);
    float2 dec = make_float2(1.f / (1.f + expf(-dre[d])), dim_[d]);
    float2 f = make_float2(fre[idx], fim[idx]);
    float2 fn = cmulf(f, dec);
    fn.x += xm[b * 2 * D + d];
    fn.y += xm[b * 2 * D + D + d];
    g_fre[idx] = fn.x;
    g_fim[idx] = fn.y;
    out[2 * TB * D + idx] = fn.x;
    out[2 * TB * D + BATCH * D + idx] = fn.y;
}

__global__ void k_source(const float* __restrict__ proj) {
    int idx = blockIdx.x * 256 + threadIdx.x;
    int b = idx >> 10, d = idx & (D - 1);
    float2 src = make_float2(proj[b * 2 * D + d], proj[b * 2 * D + D + d]);
    g_Sv[idx] = cmulf(g_opf[d], src);
}

__global__ void k_tsmall() {
    int i = blockIdx.x;
    int tid = threadIdx.x;
    float2 part[BATCH];
#pragma unroll
    for (int b = 0; b < BATCH; ++b) part[b] = make_float2(0.f, 0.f);
    for (int j = tid; j < D; j += 128) {
        float2 m = make_float2(g_Mpl[(size_t)i * 2048 + j], g_Mpl[(size_t)i * 2048 + D + j]);
#pragma unroll
        for (int b = 0; b < BATCH; ++b) {
            float2 sv = g_Sv[b * D + j];
            part[b].x = fmaf(m.x, sv.x, fmaf(-m.y, sv.y, part[b].x));
            part[b].y = fmaf(m.x, sv.y, fmaf(m.y, sv.x, part[b].y));
        }
    }
    __shared__ float2 red[BATCH][128];
#pragma unroll
    for (int b = 0; b < BATCH; ++b) red[b][tid] = part[b];
    __syncthreads();
    if (tid < BATCH) {
        float2 sv = make_float2(0.f, 0.f);
#pragma unroll 8
        for (int j = 0; j < 128; ++j) { sv.x += red[tid][j].x; sv.y += red[tid][j].y; }
        g_t[tid * D + i] = sv;
    }
}

__global__ void k_pack(const float* __restrict__ hre, const float* __restrict__ him,
                       const float* __restrict__ xre, const float* __restrict__ xim) {
    int idx = blockIdx.x * 256 + threadIdx.x;
    int n = idx >> 10, k = idx & (D - 1);
    size_t rb = (size_t)n * 4096;
    g_HX[rb + k] = hre[idx];
    g_HX[rb + D + k] = xre[idx];
    g_HX[rb + 2 * D + k] = him[idx];
    g_HX[rb + 3 * D + k] = xim[idx];
}

__global__ void k_epi(float* __restrict__ out) {
    int idx = blockIdx.x * 256 + threadIdx.x;
    int n = idx >> 10, i = idx & (D - 1);
    int b = n >> 8;
    float2 tv = g_t[b * D + i];
    out[idx] = g_Cre[idx] + tv.x;
    out[TB * D + idx] = g_Cim[idx] + tv.y;
}

// ---------- host ----------
static float* symf(const void* s) {
    void* p = nullptr;
    cudaGetSymbolAddress(&p, s);
    return (float*)p;
}
static float2* symf2(const void* s) {
    void* p = nullptr;
    cudaGetSymbolAddress(&p, s);
    return (float2*)p;
}

static GP mk(const float* A, const float* B, float* Cre, float* Cim, int ldc,
             const float* Ere, const float* Eim, int lde, float sr, float si) {
    GP p;
    p.A = A; p.B = B; p.Cre = Cre; p.Cim = Cim; p.ldc = ldc;
    p.Ere = Ere; p.Eim = Eim; p.lde = lde; p.sgnr = sr; p.sgni = si;
    return p;
}

static void gemm_full(const GP& a, const GP& b, int Kc, int Mrows, int nz) {
    dim3 g(Mrows / 128, 16, nz);
    hmma_gemm<<<g, 256>>>(a, b, Kc, 0);
}
static void gemm_tri(const GP& a, const GP& b) {
    dim3 g(72, 1, 2);
    hmma_gemm<<<g, 256>>>(a, b, D, 1);
}

extern "C" void kernel_launch(void* const* d_in, const int* in_sizes, int n_in,
                              void* d_out, int out_size) {
    const float* h_re = (const float*)d_in[0];
    const float* h_im = (const float*)d_in[1];
    const float* x_re = (const float*)d_in[2];
    const float* x_im = (const float*)d_in[3];
    const float* xg_re = (const float*)d_in[4];
    const float* xg_im = (const float*)d_in[5];
    const float* fl_re = (const float*)d_in[6];
    const float* fl_im = (const float*)d_in[7];
    const float* dt = (const float*)d_in[8];
    const float* u_re = (const float*)d_in[9];
    const float* u_im = (const float*)d_in[10];
    const float* v_re = (const float*)d_in[11];
    const float* v_im = (const float*)d_in[12];
    const float* lsig = (const float*)d_in[13];
    const float* dec_re = (const float*)d_in[14];
    const float* dec_im = (const float*)d_in[15];
    const float* mix_w = (const float*)d_in[16];
    const float* mix_b = (const float*)d_in[17];
    const float* proj_w = (const float*)d_in[18];
    const float* proj_b = (const float*)d_in[19];
    const float* ld_ = (const float*)d_in[20];
    const float* lf_ = (const float*)d_in[21];
    const float* law_re = (const float*)d_in[22];
    const float* law_im = (const float*)d_in[23];
    float* out = (float*)d_out;

    float* AsU = symf(g_AsU); float* AsV = symf(g_AsV);
    float* pAU = symf(g_pAU); float* pAV = symf(g_pAV);
    float* pBU = symf(g_pBU); float* pBV = symf(g_pBV);
    float* a0U = symf(g_a0U); float* a0V = symf(g_a0V);
    float* a1U = symf(g_a1U); float* a1V = symf(g_a1V);
    float* UV0 = symf(g_UV0); float* UV1 = symf(g_UV1);
    float* Mpl = symf(g_Mpl); float* X = symf(g_X);
    float* Us = symf(g_Us);   float* Usi = symf(g_Usi);
    float* Md = symf(g_Md);   float* Mf = symf(g_Mf);
    float* W = symf(g_W);     float* HX = symf(g_HX);
    float* Cre = symf(g_Cre); float* Cim = symf(g_Cim);
    float2* sd = symf2(g_s);  float2* sinv = symf2(g_sinv);
    float2* opd = symf2(g_opd); float2* opf = symf2(g_opf);
    float* xm = symf(g_xm);
    float* fre = symf(g_fre); float* fim = symf(g_fim);
    float* proj = symf(g_proj);

    dim3 g2(4096, 2);
    // build A for both chains
    k_buildA2<<<g2, 256>>>(AsU, AsV, u_re, u_im, v_re, v_im);

    // P2 = A*A (Hermitian, tri) ; A skew => B-op sgn (-1, +1)
    gemm_tri(mk(AsU, AsU, pAU, pAU + D, 2048, 0, 0, 0, -1.f, 1.f),
             mk(AsV, AsV, pAV, pAV + D, 2048, 0, 0, 0, -1.f, 1.f));
    k_mirror2<<<g2, 256>>>(pAU, pAV);
    // ACC0 = I + 2A + P2
    k_g02<<<g2, 256>>>(a0U, AsU, pAU, a0V, AsV, pAV);
    // ACC1 = ACC0 * (I + P2)   (P Hermitian => sgn (1,-1))
    gemm_full(mk(a0U, pAU, a1U, a1U + D, 2048, a0U, a0U + D, 2048, 1.f, -1.f),
              mk(a0V, pAV, a1V, a1V + D, 2048, a0V, a0V + D, 2048, 1.f, -1.f), D, D, 2);
    // P4 = P2*P2 (tri)
    gemm_tri(mk(pAU, pAU, pBU, pBU + D, 2048, 0, 0, 0, 1.f, -1.f),
             mk(pAV, pAV, pBV, pBV + D, 2048, 0, 0, 0, 1.f, -1.f));
    k_mirror2<<<g2, 256>>>(pBU, pBV);
    // ACC2
    gemm_full(mk(a1U, pBU, a0U, a0U + D, 2048, a1U, a1U + D, 2048, 1.f, -1.f),
              mk(a1V, pBV, a0V, a0V + D, 2048, a1V, a1V + D, 2048, 1.f, -1.f), D, D, 2);
    // P8
    gemm_tri(mk(pBU, pBU, pAU, pAU + D, 2048, 0, 0, 0, 1.f, -1.f),
             mk(pBV, pBV, pAV, pAV + D, 2048, 0, 0, 0, 1.f, -1.f));
    k_mirror2<<<g2, 256>>>(pAU, pAV);
    // ACC3
    gemm_full(mk(a0U, pAU, a1U, a1U + D, 2048, a0U, a0U + D, 2048, 1.f, -1.f),
              mk(a0V, pAV, a1V, a1V + D, 2048, a0V, a0V + D, 2048, 1.f, -1.f), D, D, 2);
    // P16
    gemm_tri(mk(pAU, pAU, pBU, pBU + D, 2048, 0, 0, 0, 1.f, -1.f),
             mk(pAV, pAV, pBV, pBV + D, 2048, 0, 0, 0, 1.f, -1.f));
    k_mirror2<<<g2, 256>>>(pBU, pBV);
    // UV = ACC3 * (I + P16)
    gemm_full(mk(a1U, pBU, UV0, UV0 + D, 2048, a1U, a1U + D, 2048, 1.f, -1.f),
              mk(a1V, pBV, UV1, UV1 + D, 2048, a1V, a1V + D, 2048, 1.f, -1.f), D, D, 2);

    k_scales<<<4, 256>>>(lsig);
    k_ops<<<4, 256>>>(ld_, lf_, law_re, law_im, dt);

    // Us = U*s, Usi = U*s^-1 (fused)
    k_colscale2<<<g2, 256>>>(Us, sd, Usi, sinv, UV0);
    // M = (U s) V^H ; X = (U s^-1) V^H  (fused; B=V conj rows => (1,-1))
    gemm_full(mk(Us, UV1, Mpl, Mpl + D, 2048, 0, 0, 0, 1.f, -1.f),
              mk(Usi, UV1, X, X + D, 2048, 0, 0, 0, 1.f, -1.f), D, D, 2);
    // Md = M*opd, Mf = M*opf (fused)
    k_colscale2<<<g2, 256>>>(Md, opd, Mf, opf, Mpl);
    // W1 = Md @ Minv ; W2 = Mf @ Minv (fused; Minv rows = conj rows of X)
    gemm_full(mk(Md, X, W, W + 2 * D, 4096, 0, 0, 0, 1.f, -1.f),
              mk(Mf, X, W + D, W + 3 * D, 4096, 0, 0, 0, 1.f, -1.f), D, D, 2);

    k_smallgemm<<<2 * D, 128>>>(xg_re, xg_im, mix_w, mix_b, xm);
    k_flux<<<BATCH * D / 256, 256>>>(fl_re, fl_im, dec_re, dec_im, xm, out);
    k_smallgemm<<<2 * D, 128>>>(fre, fim, proj_w, proj_b, proj);
    k_source<<<BATCH * D / 256, 256>>>(proj);
    k_tsmall<<<D, 128>>>();

    k_pack<<<TB * D / 256, 256>>>(h_re, h_im, x_re, x_im);
    GP pm = mk(HX, W, Cre, Cim, D, 0, 0, 0, 1.f, 1.f);
    gemm_full(pm, pm, 2 * D, TB, 1);  // main
    k_epi<<<TB * D / 256, 256>>>(out);

    (void)in_sizes; (void)n_in; (void)out_size;
}

// round 13
// speedup vs baseline: 1.1520x; 1.0029x over previous
#include <cuda_runtime.h>
#include <cuda_bf16.h>
#include <math.h>
#include <stdint.h>

#define D 1024
#define TB 4096
#define BATCH 16
typedef unsigned long long ull;

// ---------- scratch: plane-row format, row i = [re(Kc) | im(Kc)], ld 2048 ----------
__device__ __align__(16) float g_AsU[D * 2 * D];
__device__ __align__(16) float g_AsV[D * 2 * D];
__device__ __align__(16) float g_pAU[D * 2 * D];
__device__ __align__(16) float g_pAV[D * 2 * D];
__device__ __align__(16) float g_pBU[D * 2 * D];
__device__ __align__(16) float g_pBV[D * 2 * D];
__device__ __align__(16) float g_a0U[D * 2 * D];
__device__ __align__(16) float g_a0V[D * 2 * D];
__device__ __align__(16) float g_a1U[D * 2 * D];
__device__ __align__(16) float g_a1V[D * 2 * D];
__device__ __align__(16) float g_UV0[D * 2 * D];
__device__ __align__(16) float g_UV1[D * 2 * D];
__device__ __align__(16) float g_Mpl[D * 2 * D];
__device__ __align__(16) float g_X  [D * 2 * D];
__device__ __align__(16) float g_Us [D * 2 * D];
__device__ __align__(16) float g_Usi[D * 2 * D];
__device__ __align__(16) float g_Md [D * 2 * D];
__device__ __align__(16) float g_Mf [D * 2 * D];
__device__ __align__(16) float g_W  [D * 4 * D];
__device__ __align__(16) float g_HX [TB * 4 * D];
__device__ __align__(16) float g_Cre[TB * D];
__device__ __align__(16) float g_Cim[TB * D];

__device__ float2 g_s[D];
__device__ float2 g_sinv[D];
__device__ float2 g_opd[D];
__device__ float2 g_opf[D];
__device__ float  g_xm  [BATCH * 2 * D];
__device__ float  g_fre [BATCH * D];
__device__ float  g_fim [BATCH * D];
__device__ float  g_proj[BATCH * 2 * D];
__device__ float2 g_Sv  [BATCH * D];
__device__ float2 g_t   [BATCH * D];

__device__ __forceinline__ float2 cmulf(float2 a, float2 b) {
    return make_float2(fmaf(a.x, b.x, -a.y * b.y), fmaf(a.x, b.y, a.y * b.x));
}

__device__ __forceinline__ uint32_t smem_u32(const void* p) {
    uint32_t a;
    asm("{ .reg .u64 t; cvta.to.shared.u64 t, %1; cvt.u32.u64 %0, t; }" : "=r"(a) : "l"(p));
    return a;
}

__device__ __forceinline__ void bsplit(float a, float b, uint32_t& h, uint32_t& l) {
    __nv_bfloat16 ha = __float2bfloat16_rn(a), hb = __float2bfloat16_rn(b);
    __nv_bfloat16 la = __float2bfloat16_rn(a - __bfloat162float(ha));
    __nv_bfloat16 lb = __float2bfloat16_rn(b - __bfloat162float(hb));
    __nv_bfloat162 H(ha, hb), L(la, lb);
    h = reinterpret_cast<uint32_t&>(H);
    l = reinterpret_cast<uint32_t&>(L);
}

__device__ __forceinline__ void cvt8(float4 u, float4 v, float s, uint4& H, uint4& L) {
    uint32_t h0, h1, h2, h3, l0, l1, l2, l3;
    bsplit(u.x * s, u.y * s, h0, l0);
    bsplit(u.z * s, u.w * s, h1, l1);
    bsplit(v.x * s, v.y * s, h2, l2);
    bsplit(v.z * s, v.w * s, h3, l3);
    H = make_uint4(h0, h1, h2, h3);
    L = make_uint4(l0, l1, l2, l3);
}

__device__ __forceinline__ void ldm_x4(uint32_t* r, uint32_t addr) {
    asm volatile("ldmatrix.sync.aligned.m8n8.x4.shared.b16 {%0,%1,%2,%3}, [%4];"
                 : "=r"(r[0]), "=r"(r[1]), "=r"(r[2]), "=r"(r[3]) : "r"(addr));
}
__device__ __forceinline__ void mma16816(float* d, const uint32_t* a, const uint32_t* b) {
    asm volatile(
        "mma.sync.aligned.m16n8k16.row.col.f32.bf16.bf16.f32 "
        "{%0,%1,%2,%3}, {%4,%5,%6,%7}, {%8,%9}, {%0,%1,%2,%3};"
        : "+f"(d[0]), "+f"(d[1]), "+f"(d[2]), "+f"(d[3])
        : "r"(a[0]), "r"(a[1]), "r"(a[2]), "r"(a[3]), "r"(b[0]), "r"(b[1]));
}

__device__ __forceinline__ uint32_t swz(int row, int chunk) {
    return (uint32_t)(row * 64 + ((chunk ^ ((row >> 1) & 3)) << 4));
}

// ---------- HMMA GEMM body ----------
struct GP {
    const float* A;
    const float* B;
    float* Cre; float* Cim; int ldc;
    const float* Ere; const float* Eim; int lde;
    float sgnr, sgni;
};

#define A_HI 0
#define A_LO 8192
#define B_HI 16384
#define B_LO 24576

__device__ __forceinline__ void gemm_body(const GP& p, int Kc, int m0, int n0) {
    __shared__ __align__(128) uint8_t sm[32768];
    const uint32_t sb = smem_u32(sm);
    const int tid = threadIdx.x;
    const int lane = tid & 31;
    const int wid = tid >> 5;
    const int wm = (wid & 1) * 64;
    const int wn = (wid >> 1) * 32;
    const int K2 = 2 * Kc;
    const int Nc = D;
    const int isim_n = (n0 >= Nc);
    const int nsrc0 = n0 - (isim_n ? Nc : 0);
    const int T = K2 >> 5;

    float acc[4][4][4];
#pragma unroll
    for (int i = 0; i < 4; ++i)
#pragma unroll
        for (int j = 0; j < 4; ++j)
#pragma unroll
            for (int k = 0; k < 4; ++k) acc[i][j][k] = 0.f;

    float4 sa[2][2], sbv[2][2];

    auto stage = [&](int t) {
        const int kb = t << 5;
        const int isim_k = (kb >= Kc);
        const int qoff = kb - (isim_k ? Kc : 0);
        const int pl = isim_n ? (1 - isim_k) : isim_k;
        const int bcol = pl * Kc + qoff;
#pragma unroll
        for (int i = 0; i < 2; ++i) {
            int task = tid + (i << 8);
            int row = task >> 2, c = task & 3;
            const float* ap = p.A + (size_t)(m0 + row) * K2 + kb + c * 8;
            sa[i][0] = *reinterpret_cast<const float4*>(ap);
            sa[i][1] = *reinterpret_cast<const float4*>(ap + 4);
            const float* bp = p.B + (size_t)(nsrc0 + row) * K2 + bcol + c * 8;
            sbv[i][0] = *reinterpret_cast<const float4*>(bp);
            sbv[i][1] = *reinterpret_cast<const float4*>(bp + 4);
        }
    };
    auto sts = [&](int t) {
        const int kb = t << 5;
        const int isim_k = (kb >= Kc);
        const int pl = isim_n ? (1 - isim_k) : isim_k;
        const float sg = ((!isim_n && isim_k) ? -1.f : 1.f) * (pl ? p.sgni : p.sgnr);
#pragma unroll
        for (int i = 0; i < 2; ++i) {
            int task = tid + (i << 8);
            int row = task >> 2, c = task & 3;
            uint32_t off = swz(row, c);
            uint4 H, L;
            cvt8(sa[i][0], sa[i][1], 1.f, H, L);
            *reinterpret_cast<uint4*>(sm + A_HI + off) = H;
            *reinterpret_cast<uint4*>(sm + A_LO + off) = L;
            cvt8(sbv[i][0], sbv[i][1], sg, H, L);
            *reinterpret_cast<uint4*>(sm + B_HI + off) = H;
            *reinterpret_cast<uint4*>(sm + B_LO + off) = L;
        }
    };

    stage(0);
    for (int t = 0; t < T; ++t) {
        sts(t);
        __syncthreads();
        if (t + 1 < T) stage(t + 1);
#pragma unroll
        for (int k16 = 0; k16 < 2; ++k16) {
            uint32_t ah[4][4], al[4][4], bh[4][2], bl[4][2];
            int amat = lane >> 3;
            int arow_off = (lane & 7) + ((amat & 1) << 3);
            int achk = 2 * k16 + (amat >> 1);
#pragma unroll
            for (int mf = 0; mf < 4; ++mf) {
                int r = wm + mf * 16 + arow_off;
                uint32_t off = swz(r, achk);
                ldm_x4(ah[mf], sb + A_HI + off);
                ldm_x4(al[mf], sb + A_LO + off);
            }
            // B: smem holds Bop[n][k] (N x K row-major) -> non-trans fragments.
            // x4 loads 2 nf-groups x 2 k-chunks per instruction; per-matrix register
            // distribution identical to x2, so values are bit-identical.
            int grp = lane >> 3;
#pragma unroll
            for (int nfp = 0; nfp < 2; ++nfp) {
                int nf_local = nfp * 2 + (grp >> 1);
                int chunk = 2 * k16 + (grp & 1);
                int r = wn + nf_local * 8 + (lane & 7);
                uint32_t off = swz(r, chunk);
                uint32_t tr[4];
                ldm_x4(tr, sb + B_HI + off);
                bh[nfp * 2][0] = tr[0]; bh[nfp * 2][1] = tr[1];
                bh[nfp * 2 + 1][0] = tr[2]; bh[nfp * 2 + 1][1] = tr[3];
                ldm_x4(tr, sb + B_LO + off);
                bl[nfp * 2][0] = tr[0]; bl[nfp * 2][1] = tr[1];
                bl[nfp * 2 + 1][0] = tr[2]; bl[nfp * 2 + 1][1] = tr[3];
            }
#pragma unroll
            for (int mf = 0; mf < 4; ++mf)
#pragma unroll
                for (int nf = 0; nf < 4; ++nf) {
                    mma16816(acc[mf][nf], ah[mf], bh[nf]);
                    mma16816(acc[mf][nf], al[mf], bh[nf]);
                    mma16816(acc[mf][nf], ah[mf], bl[nf]);
                }
        }
        __syncthreads();
    }

    float* op = isim_n ? p.Cim : p.Cre;
    const float* ep = isim_n ? p.Eim : p.Ere;
#pragma unroll
    for (int mf = 0; mf < 4; ++mf) {
        int r0 = m0 + wm + mf * 16 + (lane >> 2);
#pragma unroll
        for (int nf = 0; nf < 4; ++nf) {
            int col = nsrc0 + wn + nf * 8 + (lane & 3) * 2;
            float2 v0 = make_float2(acc[mf][nf][0], acc[mf][nf][1]);
            float2 v1 = make_float2(acc[mf][nf][2], acc[mf][nf][3]);
            if (p.Ere) {
                v0.x += ep[(size_t)r0 * p.lde + col];
                v0.y += ep[(size_t)r0 * p.lde + col + 1];
                v1.x += ep[(size_t)(r0 + 8) * p.lde + col];
                v1.y += ep[(size_t)(r0 + 8) * p.lde + col + 1];
            }
            *reinterpret_cast<float2*>(&op[(size_t)r0 * p.ldc + col]) = v0;
            *reinterpret_cast<float2*>(&op[(size_t)(r0 + 8) * p.ldc + col]) = v1;
        }
    }
}

__device__ __forceinline__ void tri_decode(int k, int& m0, int& n0) {
    int plane = 0;
    if (k >= 36) { plane = 1; k -= 36; }
    int mi = 0;
    while (k >= 8 - mi) { k -= 8 - mi; ++mi; }
    m0 = mi * 128;
    n0 = plane * D + (mi + k) * 128;
}

// regular launcher: tri=0 grid (Mtiles, 16, nz) ; tri=1 grid (72,1,2)
__global__ void __launch_bounds__(256, 1) hmma_gemm(GP p0, GP p1, int Kc, int tri) {
    const GP p = blockIdx.z ? p1 : p0;
    int m0, n0;
    if (tri) {
        tri_decode(blockIdx.x, m0, n0);
    } else {
        m0 = blockIdx.x * 128;
        n0 = blockIdx.y * 128;
    }
    gemm_body(p, Kc, m0, n0);
}

// fused launcher: 400 CTAs = 2x128 full (ACC) + 2x72 tri (squaring)
__global__ void __launch_bounds__(256, 1) hmma_fused(GP a0, GP a1, GP t0, GP t1, int Kc) {
    int b = blockIdx.x;
    int m0, n0;
    if (b < 256) {
        const GP p = (b >= 128) ? a1 : a0;
        int t = b & 127;
        m0 = (t >> 4) * 128;
        n0 = (t & 15) * 128;
        gemm_body(p, Kc, m0, n0);
    } else {
        int k = b - 256;
        const GP p = (k >= 72) ? t1 : t0;
        if (k >= 72) k -= 72;
        tri_decode(k, m0, n0);
        gemm_body(p, Kc, m0, n0);
    }
}

// ---------- small kernels ----------
__global__ void k_buildA2(float* __restrict__ AU, float* __restrict__ AV,
                          const float* __restrict__ reU, const float* __restrict__ imU,
                          const float* __restrict__ reV, const float* __restrict__ imV) {
    int idx = blockIdx.x * 256 + threadIdx.x;
    int i = idx >> 10, j = idx & (D - 1);
    float* A = blockIdx.y ? AV : AU;
    const float* re = blockIdx.y ? reV : reU;
    const float* im = blockIdx.y ? imV : imU;
    A[(size_t)i * 2048 + j] = 0.5f * (re[i * D + j] - re[j * D + i]);
    A[(size_t)i * 2048 + D + j] = 0.5f * (im[i * D + j] + im[j * D + i]);
}

__global__ void k_mirror2(float* __restrict__ P0, float* __restrict__ P1) {
    int idx = blockIdx.x * 256 + threadIdx.x;
    int i = idx >> 10, j = idx & (D - 1);
    if (i <= j) return;
    float* P = blockIdx.y ? P1 : P0;
    P[(size_t)i * 2048 + j] = P[(size_t)j * 2048 + i];
    P[(size_t)i * 2048 + D + j] = -P[(size_t)j * 2048 + D + i];
}

__global__ void k_g02(float* __restrict__ a0U, const float* __restrict__ AU,
                      const float* __restrict__ PU, float* __restrict__ a0V,
                      const float* __restrict__ AV, const float* __restrict__ PV) {
    int idx = blockIdx.x * 256 + threadIdx.x;
    int i = idx >> 10, j = idx & (D - 1);
    float* ACC = blockIdx.y ? a0V : a0U;
    const float* A = blockIdx.y ? AV : AU;
    const float* P = blockIdx.y ? PV : PU;
    size_t rr = (size_t)i * 2048 + j, ri = rr + D;
    float dgl = (i == j) ? 1.f : 0.f;
    ACC[rr] = dgl + 2.f * A[rr] + P[rr];
    ACC[ri] = 2.f * A[ri] + P[ri];
}

__global__ void k_colscale2(float* __restrict__ d0, const float2* __restrict__ c0,
                            float* __restrict__ d1, const float2* __restrict__ c1,
                            const float* __restrict__ src) {
    int idx = blockIdx.x * 256 + threadIdx.x;
    int i = idx >> 10, j = idx & (D - 1);
    float* dst = blockIdx.y ? d1 : d0;
    float2 cc = (blockIdx.y ? c1 : c0)[j];
    size_t rr = (size_t)i * 2048 + j, ri = rr + D;
    float sr = src[rr], si = src[ri];
    dst[rr] = sr * cc.x - si * cc.y;
    dst[ri] = sr * cc.y + si * cc.x;
}

__global__ void k_scales(const float* __restrict__ ls) {
    int d = blockIdx.x * 256 + threadIdx.x;
    if (d >= D) return;
    g_s[d] = make_float2(expf(ls[d]), 0.f);
    g_sinv[d] = make_float2(expf(-ls[d]), 0.f);
}

__global__ void k_ops(const float* __restrict__ ld_, const float* __restrict__ lf_,
                      const float* __restrict__ lawre, const float* __restrict__ lawim,
                      const float* __restrict__ dtp) {
    int d = blockIdx.x * 256 + threadIdx.x;
    if (d >= D) return;
    float dtv = dtp[0];
    float lre = -expf(ld_[d]) + lawre[d];
    float lim = lf_[d] + lawim[d];
    float z = -lre;
    float sp = (z > 0.f) ? (z + log1pf(expf(-z))) : log1pf(expf(z));
    float2 Z = make_float2(-sp * dtv, lim * dtv);
    float ex = expf(Z.x);
    float sy, cy;
    sincosf(Z.y, &sy, &cy);
    float2 ez = make_float2(ex * cy, ex * sy);
    g_opd[d] = ez;
    float az2 = Z.x * Z.x + Z.y * Z.y;
    float2 phi;
    if (sqrtf(az2) < 1e-4f) {
        float2 z2 = cmulf(Z, Z);
        phi = make_float2(1.f + 0.5f * Z.x + z2.x * (1.f / 6.f), 0.5f * Z.y + z2.y * (1.f / 6.f));
    } else {
        float2 num = make_float2(ez.x - 1.f, ez.y);
        float inv = 1.f / az2;
        phi = make_float2((num.x * Z.x + num.y * Z.y) * inv, (num.y * Z.x - num.x * Z.y) * inv);
    }
    g_opf[d] = make_float2(phi.x * dtv, phi.y * dtv);
}

__global__ void k_smallgemm(const float* __restrict__ lo, const float* __restrict__ hi,
                            const float* __restrict__ w, const float* __restrict__ bias,
                            float* __restrict__ outp) {
    int o = blockIdx.x;
    int tid = threadIdx.x;
    float part[BATCH];
#pragma unroll
    for (int b = 0; b < BATCH; ++b) part[b] = 0.f;
    const float* wr = w + (size_t)o * (2 * D);
    for (int k = tid; k < 2 * D; k += 128) {
        float wv = wr[k];
        const float* src = (k < D) ? (lo + k) : (hi + (k - D));
#pragma unroll
        for (int b = 0; b < BATCH; ++b) part[b] = fmaf(src[b * D], wv, part[b]);
    }
    __shared__ float red[BATCH][128];
#pragma unroll
    for (int b = 0; b < BATCH; ++b) red[b][tid] = part[b];
    __syncthreads();
    if (tid < BATCH) {
        float sv = bias[o];
#pragma unroll 8
        for (int j = 0; j < 128; ++j) sv += red[tid][j];
        outp[tid * 2 * D + o] = sv;
    }
}

__global__ void k_flux(const float* __restrict__ fre, const float* __restrict__ fim,
                       const float* __restrict__ dre, const float* __restrict__ dim_,
                       const float* __restrict__ xm, float* __restrict__ out) {
    int idx = blockIdx.x * 256 + threadIdx.x;
    int b = idx >> 10, d = idx & (D - 1);
    float2 dec = make_float2(1.f / (1.f + expf(-dre[d])), dim_[d]);
    float2 f = make_float2(fre[idx], fim[idx]);
    float2 fn = cmulf(f, dec);
    fn.x += xm[b * 2 * D + d];
    fn.y += xm[b * 2 * D + D + d];
    g_fre[idx] = fn.x;
    g_fim[idx] = fn.y;
    out[2 * TB * D + idx] = fn.x;
    out[2 * TB * D + BATCH * D + idx] = fn.y;
}

__global__ void k_source(const float* __restrict__ proj) {
    int idx = blockIdx.x * 256 + threadIdx.x;
    int b = idx >> 10, d = idx & (D - 1);
    float2 src = make_float2(proj[b * 2 * D + d], proj[b * 2 * D + D + d]);
    g_Sv[idx] = cmulf(g_opf[d], src);
}

__global__ void k_tsmall() {
    int i = blockIdx.x;
    int tid = threadIdx.x;
    float2 part[BATCH];
#pragma unroll
    for (int b = 0; b < BATCH; ++b) part[b] = make_float2(0.f, 0.f);
    for (int j = tid; j < D; j += 128) {
        float2 m = make_float2(g_Mpl[(size_t)i * 2048 + j], g_Mpl[(size_t)i * 2048 + D + j]);
#pragma unroll
        for (int b = 0; b < BATCH; ++b) {
            float2 sv = g_Sv[b * D + j];
            part[b].x = fmaf(m.x, sv.x, fmaf(-m.y, sv.y, part[b].x));
            part[b].y = fmaf(m.x, sv.y, fmaf(m.y, sv.x, part[b].y));
        }
    }
    __shared__ float2 red[BATCH][128];
#pragma unroll
    for (int b = 0; b < BATCH; ++b) red[b][tid] = part[b];
    __syncthreads();
    if (tid < BATCH) {
        float2 sv = make_float2(0.f, 0.f);
#pragma unroll 8
        for (int j = 0; j < 128; ++j) { sv.x += red[tid][j].x; sv.y += red[tid][j].y; }
        g_t[tid * D + i] = sv;
    }
}

__global__ void k_pack(const float* __restrict__ hre, const float* __restrict__ him,
                       const float* __restrict__ xre, const float* __restrict__ xim) {
    int idx = blockIdx.x * 256 + threadIdx.x;
    int n = idx >> 10, k = idx & (D - 1);
    size_t rb = (size_t)n * 4096;
    g_HX[rb + k] = hre[idx];
    g_HX[rb + D + k] = xre[idx];
    g_HX[rb + 2 * D + k] = him[idx];
    g_HX[rb + 3 * D + k] = xim[idx];
}

__global__ void k_epi(float* __restrict__ out) {
    int idx = blockIdx.x * 256 + threadIdx.x;
    int n = idx >> 10, i = idx & (D - 1);
    int b = n >> 8;
    float2 tv = g_t[b * D + i];
    out[idx] = g_Cre[idx] + tv.x;
    out[TB * D + idx] = g_Cim[idx] + tv.y;
}

// ---------- host ----------
static float* symf(const void* s) {
    void* p = nullptr;
    cudaGetSymbolAddress(&p, s);
    return (float*)p;
}
static float2* symf2(const void* s) {
    void* p = nullptr;
    cudaGetSymbolAddress(&p, s);
    return (float2*)p;
}

static GP mk(const float* A, const float* B, float* Cre, float* Cim, int ldc,
             const float* Ere, const float* Eim, int lde, float sr, float si) {
    GP p;
    p.A = A; p.B = B; p.Cre = Cre; p.Cim = Cim; p.ldc = ldc;
    p.Ere = Ere; p.Eim = Eim; p.lde = lde; p.sgnr = sr; p.sgni = si;
    return p;
}

static void gemm_full(const GP& a, const GP& b, int Kc, int Mrows, int nz) {
    dim3 g(Mrows / 128, 16, nz);
    hmma_gemm<<<g, 256>>>(a, b, Kc, 0);
}
static void gemm_tri(const GP& a, const GP& b) {
    dim3 g(72, 1, 2);
    hmma_gemm<<<g, 256>>>(a, b, D, 1);
}
static void gemm_fused(const GP& a0, const GP& a1, const GP& t0, const GP& t1) {
    hmma_fused<<<400, 256>>>(a0, a1, t0, t1, D);
}

extern "C" void kernel_launch(void* const* d_in, const int* in_sizes, int n_in,
                              void* d_out, int out_size) {
    const float* h_re = (const float*)d_in[0];
    const float* h_im = (const float*)d_in[1];
    const float* x_re = (const float*)d_in[2];
    const float* x_im = (const float*)d_in[3];
    const float* xg_re = (const float*)d_in[4];
    const float* xg_im = (const float*)d_in[5];
    const float* fl_re = (const float*)d_in[6];
    const float* fl_im = (const float*)d_in[7];
    const float* dt = (const float*)d_in[8];
    const float* u_re = (const float*)d_in[9];
    const float* u_im = (const float*)d_in[10];
    const float* v_re = (const float*)d_in[11];
    const float* v_im = (const float*)d_in[12];
    const float* lsig = (const float*)d_in[13];
    const float* dec_re = (const float*)d_in[14];
    const float* dec_im = (const float*)d_in[15];
    const float* mix_w = (const float*)d_in[16];
    const float* mix_b = (const float*)d_in[17];
    const float* proj_w = (const float*)d_in[18];
    const float* proj_b = (const float*)d_in[19];
    const float* ld_ = (const float*)d_in[20];
    const float* lf_ = (const float*)d_in[21];
    const float* law_re = (const float*)d_in[22];
    const float* law_im = (const float*)d_in[23];
    float* out = (float*)d_out;

    float* AsU = symf(g_AsU); float* AsV = symf(g_AsV);
    float* pAU = symf(g_pAU); float* pAV = symf(g_pAV);
    float* pBU = symf(g_pBU); float* pBV = symf(g_pBV);
    float* a0U = symf(g_a0U); float* a0V = symf(g_a0V);
    float* a1U = symf(g_a1U); float* a1V = symf(g_a1V);
    float* UV0 = symf(g_UV0); float* UV1 = symf(g_UV1);
    float* Mpl = symf(g_Mpl); float* X = symf(g_X);
    float* Us = symf(g_Us);   float* Usi = symf(g_Usi);
    float* Md = symf(g_Md);   float* Mf = symf(g_Mf);
    float* W = symf(g_W);     float* HX = symf(g_HX);
    float* Cre = symf(g_Cre); float* Cim = symf(g_Cim);
    float2* sd = symf2(g_s);  float2* sinv = symf2(g_sinv);
    float2* opd = symf2(g_opd); float2* opf = symf2(g_opf);
    float* xm = symf(g_xm);
    float* fre = symf(g_fre); float* fim = symf(g_fim);
    float* proj = symf(g_proj);

    dim3 g2(4096, 2);
    k_buildA2<<<g2, 256>>>(AsU, AsV, u_re, u_im, v_re, v_im);

    // P2 = A*A (Hermitian, tri); A skew => B-op sgn (-1, +1)
    gemm_tri(mk(AsU, AsU, pAU, pAU + D, 2048, 0, 0, 0, -1.f, 1.f),
             mk(AsV, AsV, pAV, pAV + D, 2048, 0, 0, 0, -1.f, 1.f));
    k_mirror2<<<g2, 256>>>(pAU, pAV);
    k_g02<<<g2, 256>>>(a0U, AsU, pAU, a0V, AsV, pAV);

    // fused: ACC1 = ACC0*(I+P2) + P4 = P2*P2 (tri)
    gemm_fused(mk(a0U, pAU, a1U, a1U + D, 2048, a0U, a0U + D, 2048, 1.f, -1.f),
               mk(a0V, pAV, a1V, a1V + D, 2048, a0V, a0V + D, 2048, 1.f, -1.f),
               mk(pAU, pAU, pBU, pBU + D, 2048, 0, 0, 0, 1.f, -1.f),
               mk(pAV, pAV, pBV, pBV + D, 2048, 0, 0, 0, 1.f, -1.f));
    k_mirror2<<<g2, 256>>>(pBU, pBV);

    // fused: ACC2 + P8
    gemm_fused(mk(a1U, pBU, a0U, a0U + D, 2048, a1U, a1U + D, 2048, 1.f, -1.f),
               mk(a1V, pBV, a0V, a0V + D, 2048, a1V, a1V + D, 2048, 1.f, -1.f),
               mk(pBU, pBU, pAU, pAU + D, 2048, 0, 0, 0, 1.f, -1.f),
               mk(pBV, pBV, pAV, pAV + D, 2048, 0, 0, 0, 1.f, -1.f));
    k_mirror2<<<g2, 256>>>(pAU, pAV);

    // fused: ACC3 + P16
    gemm_fused(mk(a0U, pAU, a1U, a1U + D, 2048, a0U, a0U + D, 2048, 1.f, -1.f),
               mk(a0V, pAV, a1V, a1V + D, 2048, a0V, a0V + D, 2048, 1.f, -1.f),
               mk(pAU, pAU, pBU, pBU + D, 2048, 0, 0, 0, 1.f, -1.f),
               mk(pAV, pAV, pBV, pBV + D, 2048, 0, 0, 0, 1.f, -1.f));
    k_mirror2<<<g2, 256>>>(pBU, pBV);

    // UV = ACC3 * (I + P16)
    gemm_full(mk(a1U, pBU, UV0, UV0 + D, 2048, a1U, a1U + D, 2048, 1.f, -1.f),
              mk(a1V, pBV, UV1, UV1 + D, 2048, a1V, a1V + D, 2048, 1.f, -1.f), D, D, 2);

    k_scales<<<4, 256>>>(lsig);
    k_ops<<<4, 256>>>(ld_, lf_, law_re, law_im, dt);

    k_colscale2<<<g2, 256>>>(Us, sd, Usi, sinv, UV0);
    gemm_full(mk(Us, UV1, Mpl, Mpl + D, 2048, 0, 0, 0, 1.f, -1.f),
              mk(Usi, UV1, X, X + D, 2048, 0, 0, 0, 1.f, -1.f), D, D, 2);
    k_colscale2<<<g2, 256>>>(Md, opd, Mf, opf, Mpl);
    gemm_full(mk(Md, X, W, W + 2 * D, 4096, 0, 0, 0, 1.f, -1.f),
              mk(Mf, X, W + D, W + 3 * D, 4096, 0, 0, 0, 1.f, -1.f), D, D, 2);

    k_smallgemm<<<2 * D, 128>>>(xg_re, xg_im, mix_w, mix_b, xm);
    k_flux<<<BATCH * D / 256, 256>>>(fl_re, fl_im, dec_re, dec_im, xm, out);
    k_smallgemm<<<2 * D, 128>>>(fre, fim, proj_w, proj_b, proj);
    k_source<<<BATCH * D / 256, 256>>>(proj);
    k_tsmall<<<D, 128>>>();

    k_pack<<<TB * D / 256, 256>>>(h_re, h_im, x_re, x_im);
    GP pm = mk(HX, W, Cre, Cim, D, 0, 0, 0, 1.f, 1.f);
    gemm_full(pm, pm, 2 * D, TB, 1);  // main
    k_epi<<<TB * D / 256, 256>>>(out);

    (void)in_sizes; (void)n_in; (void)out_size;
}

// round 14
// speedup vs baseline: 1.2822x; 1.1130x over previous
#include <cuda_runtime.h>
#include <cuda_bf16.h>
#include <math.h>
#include <stdint.h>

#define D 1024
#define TB 4096
#define BATCH 16
typedef unsigned long long ull;

// ---------- scratch: plane-row format, row i = [re(Kc) | im(Kc)], ld 2048 ----------
__device__ __align__(16) float g_AsU[D * 2 * D];
__device__ __align__(16) float g_AsV[D * 2 * D];
__device__ __align__(16) float g_pAU[D * 2 * D];   // P2
__device__ __align__(16) float g_pAV[D * 2 * D];
__device__ __align__(16) float g_pBU[D * 2 * D];   // P4
__device__ __align__(16) float g_pBV[D * 2 * D];
__device__ __align__(16) float g_a1U[D * 2 * D];   // P8
__device__ __align__(16) float g_a1V[D * 2 * D];
__device__ __align__(16) float g_A3U[D * 2 * D];   // A^3
__device__ __align__(16) float g_A3V[D * 2 * D];
__device__ __align__(16) float g_P12U[D * 2 * D];
__device__ __align__(16) float g_P12V[D * 2 * D];
__device__ __align__(16) float g_P16U[D * 2 * D];
__device__ __align__(16) float g_P16V[D * 2 * D];
__device__ __align__(16) float g_a0U[D * 2 * D];   // F1
__device__ __align__(16) float g_a0V[D * 2 * D];
__device__ __align__(16) float g_F2U[D * 2 * D];
__device__ __align__(16) float g_F2V[D * 2 * D];
__device__ __align__(16) float g_F23U[D * 2 * D];
__device__ __align__(16) float g_F23V[D * 2 * D];
__device__ __align__(16) float g_UV0[D * 2 * D];
__device__ __align__(16) float g_UV1[D * 2 * D];
__device__ __align__(16) float g_Mpl[D * 2 * D];
__device__ __align__(16) float g_X  [D * 2 * D];
__device__ __align__(16) float g_Us [D * 2 * D];
__device__ __align__(16) float g_Usi[D * 2 * D];
__device__ __align__(16) float g_Md [D * 2 * D];
__device__ __align__(16) float g_Mf [D * 2 * D];
__device__ __align__(16) float g_W  [D * 4 * D];
__device__ __align__(16) float g_HX [TB * 4 * D];
__device__ __align__(16) float g_Cre[TB * D];
__device__ __align__(16) float g_Cim[TB * D];

__device__ float2 g_s[D];
__device__ float2 g_sinv[D];
__device__ float2 g_opd[D];
__device__ float2 g_opf[D];
__device__ float  g_xm  [BATCH * 2 * D];
__device__ float  g_fre [BATCH * D];
__device__ float  g_fim [BATCH * D];
__device__ float  g_proj[BATCH * 2 * D];
__device__ float2 g_Sv  [BATCH * D];
__device__ float2 g_t   [BATCH * D];

__device__ __forceinline__ float2 cmulf(float2 a, float2 b) {
    return make_float2(fmaf(a.x, b.x, -a.y * b.y), fmaf(a.x, b.y, a.y * b.x));
}

__device__ __forceinline__ uint32_t smem_u32(const void* p) {
    uint32_t a;
    asm("{ .reg .u64 t; cvta.to.shared.u64 t, %1; cvt.u32.u64 %0, t; }" : "=r"(a) : "l"(p));
    return a;
}

__device__ __forceinline__ void bsplit(float a, float b, uint32_t& h, uint32_t& l) {
    __nv_bfloat16 ha = __float2bfloat16_rn(a), hb = __float2bfloat16_rn(b);
    __nv_bfloat16 la = __float2bfloat16_rn(a - __bfloat162float(ha));
    __nv_bfloat16 lb = __float2bfloat16_rn(b - __bfloat162float(hb));
    __nv_bfloat162 H(ha, hb), L(la, lb);
    h = reinterpret_cast<uint32_t&>(H);
    l = reinterpret_cast<uint32_t&>(L);
}

__device__ __forceinline__ void cvt8(float4 u, float4 v, float s, uint4& H, uint4& L) {
    uint32_t h0, h1, h2, h3, l0, l1, l2, l3;
    bsplit(u.x * s, u.y * s, h0, l0);
    bsplit(u.z * s, u.w * s, h1, l1);
    bsplit(v.x * s, v.y * s, h2, l2);
    bsplit(v.z * s, v.w * s, h3, l3);
    H = make_uint4(h0, h1, h2, h3);
    L = make_uint4(l0, l1, l2, l3);
}

__device__ __forceinline__ void ldm_x4(uint32_t* r, uint32_t addr) {
    asm volatile("ldmatrix.sync.aligned.m8n8.x4.shared.b16 {%0,%1,%2,%3}, [%4];"
                 : "=r"(r[0]), "=r"(r[1]), "=r"(r[2]), "=r"(r[3]) : "r"(addr));
}
__device__ __forceinline__ void mma16816(float* d, const uint32_t* a, const uint32_t* b) {
    asm volatile(
        "mma.sync.aligned.m16n8k16.row.col.f32.bf16.bf16.f32 "
        "{%0,%1,%2,%3}, {%4,%5,%6,%7}, {%8,%9}, {%0,%1,%2,%3};"
        : "+f"(d[0]), "+f"(d[1]), "+f"(d[2]), "+f"(d[3])
        : "r"(a[0]), "r"(a[1]), "r"(a[2]), "r"(a[3]), "r"(b[0]), "r"(b[1]));
}

__device__ __forceinline__ uint32_t swz(int row, int chunk) {
    return (uint32_t)(row * 64 + ((chunk ^ ((row >> 1) & 3)) << 4));
}

// ---------- HMMA GEMM body ----------
struct GP {
    const float* A;
    const float* B;
    float* Cre; float* Cim; int ldc;
    const float* Ere; const float* Eim; int lde;
    float sgnr, sgni;
    int mirror;  // 0 none; +1 Hermitian; -1 skew-Hermitian (tri mode)
};

#define A_HI 0
#define A_LO 8192
#define B_HI 16384
#define B_LO 24576

__device__ __forceinline__ void gemm_body(const GP& p, int Kc, int m0, int n0) {
    __shared__ __align__(128) uint8_t sm[32768];
    const uint32_t sb = smem_u32(sm);
    const int tid = threadIdx.x;
    const int lane = tid & 31;
    const int wid = tid >> 5;
    const int wm = (wid & 1) * 64;
    const int wn = (wid >> 1) * 32;
    const int K2 = 2 * Kc;
    const int Nc = D;
    const int isim_n = (n0 >= Nc);
    const int nsrc0 = n0 - (isim_n ? Nc : 0);
    const int T = K2 >> 5;

    float acc[4][4][4];
#pragma unroll
    for (int i = 0; i < 4; ++i)
#pragma unroll
        for (int j = 0; j < 4; ++j)
#pragma unroll
            for (int k = 0; k < 4; ++k) acc[i][j][k] = 0.f;

    float4 sa[2][2], sbv[2][2];

    auto stage = [&](int t) {
        const int kb = t << 5;
        const int isim_k = (kb >= Kc);
        const int qoff = kb - (isim_k ? Kc : 0);
        const int pl = isim_n ? (1 - isim_k) : isim_k;
        const int bcol = pl * Kc + qoff;
#pragma unroll
        for (int i = 0; i < 2; ++i) {
            int task = tid + (i << 8);
            int row = task >> 2, c = task & 3;
            const float* ap = p.A + (size_t)(m0 + row) * K2 + kb + c * 8;
            sa[i][0] = *reinterpret_cast<const float4*>(ap);
            sa[i][1] = *reinterpret_cast<const float4*>(ap + 4);
            const float* bp = p.B + (size_t)(nsrc0 + row) * K2 + bcol + c * 8;
            sbv[i][0] = *reinterpret_cast<const float4*>(bp);
            sbv[i][1] = *reinterpret_cast<const float4*>(bp + 4);
        }
    };
    auto sts = [&](int t) {
        const int kb = t << 5;
        const int isim_k = (kb >= Kc);
        const int pl = isim_n ? (1 - isim_k) : isim_k;
        const float sg = ((!isim_n && isim_k) ? -1.f : 1.f) * (pl ? p.sgni : p.sgnr);
#pragma unroll
        for (int i = 0; i < 2; ++i) {
            int task = tid + (i << 8);
            int row = task >> 2, c = task & 3;
            uint32_t off = swz(row, c);
            uint4 H, L;
            cvt8(sa[i][0], sa[i][1], 1.f, H, L);
            *reinterpret_cast<uint4*>(sm + A_HI + off) = H;
            *reinterpret_cast<uint4*>(sm + A_LO + off) = L;
            cvt8(sbv[i][0], sbv[i][1], sg, H, L);
            *reinterpret_cast<uint4*>(sm + B_HI + off) = H;
            *reinterpret_cast<uint4*>(sm + B_LO + off) = L;
        }
    };

    stage(0);
    for (int t = 0; t < T; ++t) {
        sts(t);
        __syncthreads();
        if (t + 1 < T) stage(t + 1);
#pragma unroll
        for (int k16 = 0; k16 < 2; ++k16) {
            uint32_t ah[4][4], al[4][4], bh[4][2], bl[4][2];
            int amat = lane >> 3;
            int arow_off = (lane & 7) + ((amat & 1) << 3);
            int achk = 2 * k16 + (amat >> 1);
#pragma unroll
            for (int mf = 0; mf < 4; ++mf) {
                int r = wm + mf * 16 + arow_off;
                uint32_t off = swz(r, achk);
                ldm_x4(ah[mf], sb + A_HI + off);
                ldm_x4(al[mf], sb + A_LO + off);
            }
            int grp = lane >> 3;
#pragma unroll
            for (int nfp = 0; nfp < 2; ++nfp) {
                int nf_local = nfp * 2 + (grp >> 1);
                int chunk = 2 * k16 + (grp & 1);
                int r = wn + nf_local * 8 + (lane & 7);
                uint32_t off = swz(r, chunk);
                uint32_t tr[4];
                ldm_x4(tr, sb + B_HI + off);
                bh[nfp * 2][0] = tr[0]; bh[nfp * 2][1] = tr[1];
                bh[nfp * 2 + 1][0] = tr[2]; bh[nfp * 2 + 1][1] = tr[3];
                ldm_x4(tr, sb + B_LO + off);
                bl[nfp * 2][0] = tr[0]; bl[nfp * 2][1] = tr[1];
                bl[nfp * 2 + 1][0] = tr[2]; bl[nfp * 2 + 1][1] = tr[3];
            }
#pragma unroll
            for (int mf = 0; mf < 4; ++mf)
#pragma unroll
                for (int nf = 0; nf < 4; ++nf) {
                    mma16816(acc[mf][nf], ah[mf], bh[nf]);
                    mma16816(acc[mf][nf], al[mf], bh[nf]);
                    mma16816(acc[mf][nf], ah[mf], bl[nf]);
                }
        }
        __syncthreads();
    }

    float* op = isim_n ? p.Cim : p.Cre;
    const float* ep = isim_n ? p.Eim : p.Ere;
    const float ms = (float)p.mirror * (isim_n ? -1.f : 1.f);
#pragma unroll
    for (int mf = 0; mf < 4; ++mf) {
        int r0 = m0 + wm + mf * 16 + (lane >> 2);
#pragma unroll
        for (int nf = 0; nf < 4; ++nf) {
            int col = nsrc0 + wn + nf * 8 + (lane & 3) * 2;
            float2 v0 = make_float2(acc[mf][nf][0], acc[mf][nf][1]);
            float2 v1 = make_float2(acc[mf][nf][2], acc[mf][nf][3]);
            if (p.Ere) {
                v0.x += ep[(size_t)r0 * p.lde + col];
                v0.y += ep[(size_t)r0 * p.lde + col + 1];
                v1.x += ep[(size_t)(r0 + 8) * p.lde + col];
                v1.y += ep[(size_t)(r0 + 8) * p.lde + col + 1];
            }
            *reinterpret_cast<float2*>(&op[(size_t)r0 * p.ldc + col]) = v0;
            *reinterpret_cast<float2*>(&op[(size_t)(r0 + 8) * p.ldc + col]) = v1;
            if (p.mirror) {
                if (r0 != col)     op[(size_t)col * p.ldc + r0] = ms * v0.x;
                if (r0 != col + 1) op[(size_t)(col + 1) * p.ldc + r0] = ms * v0.y;
                if (r0 + 8 != col) op[(size_t)col * p.ldc + r0 + 8] = ms * v1.x;
                if (r0 + 8 != col + 1)
                    op[(size_t)(col + 1) * p.ldc + r0 + 8] = ms * v1.y;
            }
        }
    }
}

__device__ __forceinline__ void tri_decode(int k, int& m0, int& n0) {
    int plane = 0;
    if (k >= 36) { plane = 1; k -= 36; }
    int mi = 0;
    while (k >= 8 - mi) { k -= 8 - mi; ++mi; }
    m0 = mi * 128;
    n0 = plane * D + (mi + k) * 128;
}

// regular launcher: tri=0 grid (Mtiles, 16, nz) ; tri=1 grid (72,1,2)
__global__ void __launch_bounds__(256, 1) hmma_gemm(GP p0, GP p1, int Kc, int tri) {
    const GP p = blockIdx.z ? p1 : p0;
    int m0, n0;
    if (tri) {
        tri_decode(blockIdx.x, m0, n0);
    } else {
        m0 = blockIdx.x * 128;
        n0 = blockIdx.y * 128;
    }
    gemm_body(p, Kc, m0, n0);
}

// 4-way tri launcher: 288 CTAs (72 per GP)
__global__ void __launch_bounds__(256, 1) hmma_tri4(GP p0, GP p1, GP p2, GP p3, int Kc) {
    int b = blockIdx.x;
    GP p;
    if (b < 72) p = p0;
    else if (b < 144) { p = p1; b -= 72; }
    else if (b < 216) { p = p2; b -= 144; }
    else { p = p3; b -= 216; }
    int m0, n0;
    tri_decode(b, m0, n0);
    gemm_body(p, Kc, m0, n0);
}

// ---------- small kernels ----------
__global__ void k_buildA2(float* __restrict__ AU, float* __restrict__ AV,
                          const float* __restrict__ reU, const float* __restrict__ imU,
                          const float* __restrict__ reV, const float* __restrict__ imV) {
    int idx = blockIdx.x * 256 + threadIdx.x;
    int i = idx >> 10, j = idx & (D - 1);
    float* A = blockIdx.y ? AV : AU;
    const float* re = blockIdx.y ? reV : reU;
    const float* im = blockIdx.y ? imV : imU;
    A[(size_t)i * 2048 + j] = 0.5f * (re[i * D + j] - re[j * D + i]);
    A[(size_t)i * 2048 + D + j] = 0.5f * (im[i * D + j] + im[j * D + i]);
}

// F1 = I + 2A + 2P2 + 2A3 + P4
__global__ void k_F1(float* __restrict__ F1U, float* __restrict__ F1V,
                     const float* __restrict__ AU, const float* __restrict__ AV,
                     const float* __restrict__ P2U, const float* __restrict__ P2V,
                     const float* __restrict__ A3U, const float* __restrict__ A3V,
                     const float* __restrict__ P4U, const float* __restrict__ P4V) {
    int idx = blockIdx.x * 256 + threadIdx.x;
    int i = idx >> 10, j = idx & (D - 1);
    float* F = blockIdx.y ? F1V : F1U;
    const float* A = blockIdx.y ? AV : AU;
    const float* P2 = blockIdx.y ? P2V : P2U;
    const float* A3 = blockIdx.y ? A3V : A3U;
    const float* P4 = blockIdx.y ? P4V : P4U;
    size_t rr = (size_t)i * 2048 + j, ri = rr + D;
    float dgl = (i == j) ? 1.f : 0.f;
    F[rr] = dgl + 2.f * A[rr] + 2.f * P2[rr] + 2.f * A3[rr] + P4[rr];
    F[ri] = 2.f * A[ri] + 2.f * P2[ri] + 2.f * A3[ri] + P4[ri];
}

// F2 = I + P4 + P8 + P12
__global__ void k_F2(float* __restrict__ F2U, float* __restrict__ F2V,
                     const float* __restrict__ P4U, const float* __restrict__ P4V,
                     const float* __restrict__ P8U, const float* __restrict__ P8V,
                     const float* __restrict__ P12U, const float* __restrict__ P12V) {
    int idx = blockIdx.x * 256 + threadIdx.x;
    int i = idx >> 10, j = idx & (D - 1);
    float* F = blockIdx.y ? F2V : F2U;
    const float* P4 = blockIdx.y ? P4V : P4U;
    const float* P8 = blockIdx.y ? P8V : P8U;
    const float* P12 = blockIdx.y ? P12V : P12U;
    size_t rr = (size_t)i * 2048 + j, ri = rr + D;
    float dgl = (i == j) ? 1.f : 0.f;
    F[rr] = dgl + P4[rr] + P8[rr] + P12[rr];
    F[ri] = P4[ri] + P8[ri] + P12[ri];
}

__global__ void k_colscale2(float* __restrict__ d0, const float2* __restrict__ c0,
                            float* __restrict__ d1, const float2* __restrict__ c1,
                            const float* __restrict__ src) {
    int idx = blockIdx.x * 256 + threadIdx.x;
    int i = idx >> 10, j = idx & (D - 1);
    float* dst = blockIdx.y ? d1 : d0;
    float2 cc = (blockIdx.y ? c1 : c0)[j];
    size_t rr = (size_t)i * 2048 + j, ri = rr + D;
    float sr = src[rr], si = src[ri];
    dst[rr] = sr * cc.x - si * cc.y;
    dst[ri] = sr * cc.y + si * cc.x;
}

__global__ void k_scales(const float* __restrict__ ls) {
    int d = blockIdx.x * 256 + threadIdx.x;
    if (d >= D) return;
    g_s[d] = make_float2(expf(ls[d]), 0.f);
    g_sinv[d] = make_float2(expf(-ls[d]), 0.f);
}

__global__ void k_ops(const float* __restrict__ ld_, const float* __restrict__ lf_,
                      const float* __restrict__ lawre, const float* __restrict__ lawim,
                      const float* __restrict__ dtp) {
    int d = blockIdx.x * 256 + threadIdx.x;
    if (d >= D) return;
    float dtv = dtp[0];
    float lre = -expf(ld_[d]) + lawre[d];
    float lim = lf_[d] + lawim[d];
    float z = -lre;
    float sp = (z > 0.f) ? (z + log1pf(expf(-z))) : log1pf(expf(z));
    float2 Z = make_float2(-sp * dtv, lim * dtv);
    float ex = expf(Z.x);
    float sy, cy;
    sincosf(Z.y, &sy, &cy);
    float2 ez = make_float2(ex * cy, ex * sy);
    g_opd[d] = ez;
    float az2 = Z.x * Z.x + Z.y * Z.y;
    float2 phi;
    if (sqrtf(az2) < 1e-4f) {
        float2 z2 = cmulf(Z, Z);
        phi = make_float2(1.f + 0.5f * Z.x + z2.x * (1.f / 6.f), 0.5f * Z.y + z2.y * (1.f / 6.f));
    } else {
        float2 num = make_float2(ez.x - 1.f, ez.y);
        float inv = 1.f / az2;
        phi = make_float2((num.x * Z.x + num.y * Z.y) * inv, (num.y * Z.x - num.x * Z.y) * inv);
    }
    g_opf[d] = make_float2(phi.x * dtv, phi.y * dtv);
}

__global__ void k_smallgemm(const float* __restrict__ lo, const float* __restrict__ hi,
                            const float* __restrict__ w, const float* __restrict__ bias,
                            float* __restrict__ outp) {
    int o = blockIdx.x;
    int tid = threadIdx.x;
    float part[BATCH];
#pragma unroll
    for (int b = 0; b < BATCH; ++b) part[b] = 0.f;
    const float* wr = w + (size_t)o * (2 * D);
    for (int k = tid; k < 2 * D; k += 128) {
        float wv = wr[k];
        const float* src = (k < D) ? (lo + k) : (hi + (k - D));
#pragma unroll
        for (int b = 0; b < BATCH; ++b) part[b] = fmaf(src[b * D], wv, part[b]);
    }
    __shared__ float red[BATCH][128];
#pragma unroll
    for (int b = 0; b < BATCH; ++b) red[b][tid] = part[b];
    __syncthreads();
    if (tid < BATCH) {
        float sv = bias[o];
#pragma unroll 8
        for (int j = 0; j < 128; ++j) sv += red[tid][j];
        outp[tid * 2 * D + o] = sv;
    }
}

__global__ void k_flux(const float* __restrict__ fre, const float* __restrict__ fim,
                       const float* __restrict__ dre, const float* __restrict__ dim_,
                       const float* __restrict__ xm, float* __restrict__ out) {
    int idx = blockIdx.x * 256 + threadIdx.x;
    int b = idx >> 10, d = idx & (D - 1);
    float2 dec = make_float2(1.f / (1.f + expf(-dre[d])), dim_[d]);
    float2 f = make_float2(fre[idx], fim[idx]);
    float2 fn = cmulf(f, dec);
    fn.x += xm[b * 2 * D + d];
    fn.y += xm[b * 2 * D + D + d];
    g_fre[idx] = fn.x;
    g_fim[idx] = fn.y;
    out[2 * TB * D + idx] = fn.x;
    out[2 * TB * D + BATCH * D + idx] = fn.y;
}

__global__ void k_source(const float* __restrict__ proj) {
    int idx = blockIdx.x * 256 + threadIdx.x;
    int b = idx >> 10, d = idx & (D - 1);
    float2 src = make_float2(proj[b * 2 * D + d], proj[b * 2 * D + D + d]);
    g_Sv[idx] = cmulf(g_opf[d], src);
}

__global__ void k_tsmall() {
    int i = blockIdx.x;
    int tid = threadIdx.x;
    float2 part[BATCH];
#pragma unroll
    for (int b = 0; b < BATCH; ++b) part[b] = make_float2(0.f, 0.f);
    for (int j = tid; j < D; j += 128) {
        float2 m = make_float2(g_Mpl[(size_t)i * 2048 + j], g_Mpl[(size_t)i * 2048 + D + j]);
#pragma unroll
        for (int b = 0; b < BATCH; ++b) {
            float2 sv = g_Sv[b * D + j];
            part[b].x = fmaf(m.x, sv.x, fmaf(-m.y, sv.y, part[b].x));
            part[b].y = fmaf(m.x, sv.y, fmaf(m.y, sv.x, part[b].y));
        }
    }
    __shared__ float2 red[BATCH][128];
#pragma unroll
    for (int b = 0; b < BATCH; ++b) red[b][tid] = part[b];
    __syncthreads();
    if (tid < BATCH) {
        float2 sv = make_float2(0.f, 0.f);
#pragma unroll 8
        for (int j = 0; j < 128; ++j) { sv.x += red[tid][j].x; sv.y += red[tid][j].y; }
        g_t[tid * D + i] = sv;
    }
}

__global__ void k_pack(const float* __restrict__ hre, const float* __restrict__ him,
                       const float* __restrict__ xre, const float* __restrict__ xim) {
    int idx = blockIdx.x * 256 + threadIdx.x;
    int n = idx >> 10, k = idx & (D - 1);
    size_t rb = (size_t)n * 4096;
    g_HX[rb + k] = hre[idx];
    g_HX[rb + D + k] = xre[idx];
    g_HX[rb + 2 * D + k] = him[idx];
    g_HX[rb + 3 * D + k] = xim[idx];
}

__global__ void k_epi(float* __restrict__ out) {
    int idx = blockIdx.x * 256 + threadIdx.x;
    int n = idx >> 10, i = idx & (D - 1);
    int b = n >> 8;
    float2 tv = g_t[b * D + i];
    out[idx] = g_Cre[idx] + tv.x;
    out[TB * D + idx] = g_Cim[idx] + tv.y;
}

// ---------- host ----------
static float* symf(const void* s) {
    void* p = nullptr;
    cudaGetSymbolAddress(&p, s);
    return (float*)p;
}
static float2* symf2(const void* s) {
    void* p = nullptr;
    cudaGetSymbolAddress(&p, s);
    return (float2*)p;
}

static GP mk(const float* A, const float* B, float* Cre, float* Cim, int ldc,
             const float* Ere, const float* Eim, int lde, float sr, float si, int mir) {
    GP p;
    p.A = A; p.B = B; p.Cre = Cre; p.Cim = Cim; p.ldc = ldc;
    p.Ere = Ere; p.Eim = Eim; p.lde = lde; p.sgnr = sr; p.sgni = si; p.mirror = mir;
    return p;
}

static void gemm_full(const GP& a, const GP& b, int Kc, int Mrows, int nz) {
    dim3 g(Mrows / 128, 16, nz);
    hmma_gemm<<<g, 256>>>(a, b, Kc, 0);
}
static void gemm_tri(const GP& a, const GP& b) {
    dim3 g(72, 1, 2);
    hmma_gemm<<<g, 256>>>(a, b, D, 1);
}

extern "C" void kernel_launch(void* const* d_in, const int* in_sizes, int n_in,
                              void* d_out, int out_size) {
    const float* h_re = (const float*)d_in[0];
    const float* h_im = (const float*)d_in[1];
    const float* x_re = (const float*)d_in[2];
    const float* x_im = (const float*)d_in[3];
    const float* xg_re = (const float*)d_in[4];
    const float* xg_im = (const float*)d_in[5];
    const float* fl_re = (const float*)d_in[6];
    const float* fl_im = (const float*)d_in[7];
    const float* dt = (const float*)d_in[8];
    const float* u_re = (const float*)d_in[9];
    const float* u_im = (const float*)d_in[10];
    const float* v_re = (const float*)d_in[11];
    const float* v_im = (const float*)d_in[12];
    const float* lsig = (const float*)d_in[13];
    const float* dec_re = (const float*)d_in[14];
    const float* dec_im = (const float*)d_in[15];
    const float* mix_w = (const float*)d_in[16];
    const float* mix_b = (const float*)d_in[17];
    const float* proj_w = (const float*)d_in[18];
    const float* proj_b = (const float*)d_in[19];
    const float* ld_ = (const float*)d_in[20];
    const float* lf_ = (const float*)d_in[21];
    const float* law_re = (const float*)d_in[22];
    const float* law_im = (const float*)d_in[23];
    float* out = (float*)d_out;

    float* AsU = symf(g_AsU); float* AsV = symf(g_AsV);
    float* P2U = symf(g_pAU); float* P2V = symf(g_pAV);
    float* P4U = symf(g_pBU); float* P4V = symf(g_pBV);
    float* P8U = symf(g_a1U); float* P8V = symf(g_a1V);
    float* A3U = symf(g_A3U); float* A3V = symf(g_A3V);
    float* P12U = symf(g_P12U); float* P12V = symf(g_P12V);
    float* P16U = symf(g_P16U); float* P16V = symf(g_P16V);
    float* F1U = symf(g_a0U); float* F1V = symf(g_a0V);
    float* F2U = symf(g_F2U); float* F2V = symf(g_F2V);
    float* F23U = symf(g_F23U); float* F23V = symf(g_F23V);
    float* UV0 = symf(g_UV0); float* UV1 = symf(g_UV1);
    float* Mpl = symf(g_Mpl); float* X = symf(g_X);
    float* Us = symf(g_Us);   float* Usi = symf(g_Usi);
    float* Md = symf(g_Md);   float* Mf = symf(g_Mf);
    float* W = symf(g_W);     float* HX = symf(g_HX);
    float* Cre = symf(g_Cre); float* Cim = symf(g_Cim);
    float2* sd = symf2(g_s);  float2* sinv = symf2(g_sinv);
    float2* opd = symf2(g_opd); float2* opf = symf2(g_opf);
    float* xm = symf(g_xm);
    float* fre = symf(g_fre); float* fim = symf(g_fim);
    float* proj = symf(g_proj);

    dim3 g2(4096, 2);
    k_buildA2<<<g2, 256>>>(AsU, AsV, u_re, u_im, v_re, v_im);

    // P2 = A*A (Herm; A skew => B-op (-1,+1)), mirror +1
    gemm_tri(mk(AsU, AsU, P2U, P2U + D, 2048, 0, 0, 0, -1.f, 1.f, 1),
             mk(AsV, AsV, P2V, P2V + D, 2048, 0, 0, 0, -1.f, 1.f, 1));
    // A3 = A*P2 (skew; B=P2 Herm (1,-1)), P4 = P2*P2 (Herm) — 288 CTAs
    hmma_tri4<<<288, 256>>>(
        mk(AsU, P2U, A3U, A3U + D, 2048, 0, 0, 0, 1.f, -1.f, -1),
        mk(AsV, P2V, A3V, A3V + D, 2048, 0, 0, 0, 1.f, -1.f, -1),
        mk(P2U, P2U, P4U, P4U + D, 2048, 0, 0, 0, 1.f, -1.f, 1),
        mk(P2V, P2V, P4V, P4V + D, 2048, 0, 0, 0, 1.f, -1.f, 1), D);
    // P8 = P4*P4 (Herm)
    gemm_tri(mk(P4U, P4U, P8U, P8U + D, 2048, 0, 0, 0, 1.f, -1.f, 1),
             mk(P4V, P4V, P8V, P8V + D, 2048, 0, 0, 0, 1.f, -1.f, 1));
    // F1 = I + 2A + 2P2 + 2A3 + P4
    k_F1<<<g2, 256>>>(F1U, F1V, AsU, AsV, P2U, P2V, A3U, A3V, P4U, P4V);
    // P12 = P4*P8, P16 = P8*P8 (both Herm) — 288 CTAs
    hmma_tri4<<<288, 256>>>(
        mk(P4U, P8U, P12U, P12U + D, 2048, 0, 0, 0, 1.f, -1.f, 1),
        mk(P4V, P8V, P12V, P12V + D, 2048, 0, 0, 0, 1.f, -1.f, 1),
        mk(P8U, P8U, P16U, P16U + D, 2048, 0, 0, 0, 1.f, -1.f, 1),
        mk(P8V, P8V, P16V, P16V + D, 2048, 0, 0, 0, 1.f, -1.f, 1), D);
    // F2 = I + P4 + P8 + P12
    k_F2<<<g2, 256>>>(F2U, F2V, P4U, P4V, P8U, P8V, P12U, P12V);
    // F23 = F2*P16 + F2 (Herm, E-add)
    gemm_tri(mk(F2U, P16U, F23U, F23U + D, 2048, F2U, F2U + D, 2048, 1.f, -1.f, 1),
             mk(F2V, P16V, F23V, F23V + D, 2048, F2V, F2V + D, 2048, 1.f, -1.f, 1));
    // UV = F1 * F23 (full; B=F23 Herm (1,-1))
    gemm_full(mk(F1U, F23U, UV0, UV0 + D, 2048, 0, 0, 0, 1.f, -1.f, 0),
              mk(F1V, F23V, UV1, UV1 + D, 2048, 0, 0, 0, 1.f, -1.f, 0), D, D, 2);

    k_scales<<<4, 256>>>(lsig);
    k_ops<<<4, 256>>>(ld_, lf_, law_re, law_im, dt);

    k_colscale2<<<g2, 256>>>(Us, sd, Usi, sinv, UV0);
    gemm_full(mk(Us, UV1, Mpl, Mpl + D, 2048, 0, 0, 0, 1.f, -1.f, 0),
              mk(Usi, UV1, X, X + D, 2048, 0, 0, 0, 1.f, -1.f, 0), D, D, 2);
    k_colscale2<<<g2, 256>>>(Md, opd, Mf, opf, Mpl);
    gemm_full(mk(Md, X, W, W + 2 * D, 4096, 0, 0, 0, 1.f, -1.f, 0),
              mk(Mf, X, W + D, W + 3 * D, 4096, 0, 0, 0, 1.f, -1.f, 0), D, D, 2);

    k_smallgemm<<<2 * D, 128>>>(xg_re, xg_im, mix_w, mix_b, xm);
    k_flux<<<BATCH * D / 256, 256>>>(fl_re, fl_im, dec_re, dec_im, xm, out);
    k_smallgemm<<<2 * D, 128>>>(fre, fim, proj_w, proj_b, proj);
    k_source<<<BATCH * D / 256, 256>>>(proj);
    k_tsmall<<<D, 128>>>();

    k_pack<<<TB * D / 256, 256>>>(h_re, h_im, x_re, x_im);
    GP pm = mk(HX, W, Cre, Cim, D, 0, 0, 0, 1.f, 1.f, 0);
    gemm_full(pm, pm, 2 * D, TB, 1);  // main
    k_epi<<<TB * D / 256, 256>>>(out);

    (void)in_sizes; (void)n_in; (void)out_size;
}